// round 7
// baseline (speedup 1.0000x reference)
#include <cuda_runtime.h>
#include <cuda_bf16.h>
#include <math.h>
#include <stdint.h>

// ============================================================================
// CrossAttentionReader — GB300 sm_103a, round 7
//  - GEMM: tile 64x128, 256 thr, 2 CTAs/SM co-resident (grid 256)
//  - attn: 8 same-sign rows per block (8x K/V L2-traffic reuse)
// ============================================================================

#define D_MAX     1024
#define M_MAX     32768
#define ROWS_MAX  2048
#define TKK       32
#define NHEADS    16

// ---- scratch (device globals; no allocation allowed) ----
__device__ float g_r[M_MAX];
__device__ float g_wbar[D_MAX];
__device__ float g_colpart[8 * D_MAX];
__device__ int   g_posidx[TKK];
__device__ int   g_negidx[TKK];
__device__ int   g_sign[ROWS_MAX];
__device__ int   g_poslist[ROWS_MAX];
__device__ int   g_neglist[ROWS_MAX];
__device__ int   g_counts[2];
__device__ unsigned long long g_cand[2 * 1024];
__device__ float g_Kp[TKK * D_MAX];
__device__ float g_Kn[TKK * D_MAX];
__device__ float g_Vp[TKK * D_MAX];
__device__ float g_Vn[TKK * D_MAX];
__device__ float g_qfull[(size_t)ROWS_MAX * D_MAX];
__device__ __nv_bfloat16 g_xhi[(size_t)ROWS_MAX * D_MAX];
__device__ __nv_bfloat16 g_xlo[(size_t)ROWS_MAX * D_MAX];
__device__ __nv_bfloat16 g_ctxhi[(size_t)ROWS_MAX * D_MAX];
__device__ __nv_bfloat16 g_ctxlo[(size_t)ROWS_MAX * D_MAX];
__device__ __nv_bfloat16 g_Wqhi[(size_t)D_MAX * D_MAX];
__device__ __nv_bfloat16 g_Wqlo[(size_t)D_MAX * D_MAX];
__device__ __nv_bfloat16 g_Wohi[(size_t)D_MAX * D_MAX];
__device__ __nv_bfloat16 g_Wolo[(size_t)D_MAX * D_MAX];

// ============================ helpers ===================================
__device__ __forceinline__ uint32_t smem_u32(const void* p) {
    uint32_t a;
    asm("{ .reg .u64 t; cvta.to.shared.u64 t, %1; cvt.u32.u64 %0, t; }" : "=r"(a) : "l"(p));
    return a;
}
__device__ __forceinline__ void ldsm_x4(uint32_t* r, uint32_t addr) {
    asm volatile("ldmatrix.sync.aligned.m8n8.x4.shared.b16 {%0,%1,%2,%3}, [%4];"
                 : "=r"(r[0]), "=r"(r[1]), "=r"(r[2]), "=r"(r[3]) : "r"(addr));
}
__device__ __forceinline__ void mma_bf16(float* d, const uint32_t* a, const uint32_t* b) {
    asm volatile("mma.sync.aligned.m16n8k16.row.col.f32.bf16.bf16.f32 "
                 "{%0,%1,%2,%3}, {%4,%5,%6,%7}, {%8,%9}, {%0,%1,%2,%3};"
                 : "+f"(d[0]), "+f"(d[1]), "+f"(d[2]), "+f"(d[3])
                 : "r"(a[0]), "r"(a[1]), "r"(a[2]), "r"(a[3]), "r"(b[0]), "r"(b[1]));
}
#define CP_ASYNC16(sa, gp) \
    asm volatile("cp.async.cg.shared.global [%0], [%1], 16;" :: "r"(sa), "l"(gp))
#define CP_COMMIT() asm volatile("cp.async.commit_group;" ::: "memory")
#define CP_WAIT(n)  asm volatile("cp.async.wait_group %0;" :: "n"(n) : "memory")

// ---------------------------------------------------------------------------
// split fp32 -> bf16 hi/lo
// ---------------------------------------------------------------------------
__global__ void split_kernel(const float* __restrict__ src, __nv_bfloat16* __restrict__ hi,
                             __nv_bfloat16* __restrict__ lo, int n4) {
    int i = blockIdx.x * 256 + threadIdx.x;
    if (i >= n4) return;
    float4 v = ((const float4*)src)[i];
    __nv_bfloat16 h0 = __float2bfloat16(v.x), h1 = __float2bfloat16(v.y);
    __nv_bfloat16 h2 = __float2bfloat16(v.z), h3 = __float2bfloat16(v.w);
    __nv_bfloat16 l0 = __float2bfloat16(v.x - __bfloat162float(h0));
    __nv_bfloat16 l1 = __float2bfloat16(v.y - __bfloat162float(h1));
    __nv_bfloat16 l2 = __float2bfloat16(v.z - __bfloat162float(h2));
    __nv_bfloat16 l3 = __float2bfloat16(v.w - __bfloat162float(h3));
    ((__nv_bfloat162*)hi)[2 * i]     = __nv_bfloat162(h0, h1);
    ((__nv_bfloat162*)hi)[2 * i + 1] = __nv_bfloat162(h2, h3);
    ((__nv_bfloat162*)lo)[2 * i]     = __nv_bfloat162(l0, l1);
    ((__nv_bfloat162*)lo)[2 * i + 1] = __nv_bfloat162(l2, l3);
}

// ---------------------------------------------------------------------------
// zero the pos/neg counters (graph-replay safe)
// ---------------------------------------------------------------------------
__global__ void zerocnt_kernel(int* counts) {
    if (threadIdx.x < 2) counts[threadIdx.x] = 0;
}

// ---------------------------------------------------------------------------
// column sum of Wq — two-stage deterministic reduction
// ---------------------------------------------------------------------------
__global__ void colsum1_kernel(const float* __restrict__ W, float* __restrict__ part, int D) {
    int d = blockIdx.x * 256 + threadIdx.x;
    if (d >= D) return;
    int r0 = blockIdx.y * 128;
    float s = 0.f;
    for (int r = r0; r < r0 + 128; r++) s += W[(size_t)r * D + d];
    part[blockIdx.y * D + d] = s;
}
__global__ void colsum2_kernel(const float* __restrict__ part, float* __restrict__ wbar, int D) {
    int d = blockIdx.x * 256 + threadIdx.x;
    if (d >= D) return;
    float s = 0.f;
    #pragma unroll
    for (int i = 0; i < 8; i++) s += part[i * D + d];
    wbar[d] = s;
}

// ---------------------------------------------------------------------------
// per-row r[m] = sum / (sqrtD * norm)
// ---------------------------------------------------------------------------
__global__ void rowstat_kernel(const float* __restrict__ mk, float* __restrict__ r,
                               int M, int D, float sqrtD) {
    int warp = threadIdx.x >> 5, lane = threadIdx.x & 31;
    int m = blockIdx.x * 8 + warp;
    if (m >= M) return;
    const float* row = mk + (size_t)m * D;
    float s = 0.f, ss = 0.f;
    for (int j = lane * 4; j < D; j += 128) {
        float4 v = *(const float4*)(row + j);
        s  += v.x + v.y + v.z + v.w;
        ss += v.x * v.x + v.y * v.y + v.z * v.z + v.w * v.w;
    }
    #pragma unroll
    for (int off = 16; off; off >>= 1) {
        s  += __shfl_xor_sync(0xffffffffu, s, off);
        ss += __shfl_xor_sync(0xffffffffu, ss, off);
    }
    if (lane == 0) r[m] = s / (sqrtD * sqrtf(ss));
}

// ---------------------------------------------------------------------------
// sign(qm) per row; append row to pos/neg list (order-independent outputs)
// ---------------------------------------------------------------------------
__global__ void qmsign_kernel(const float* __restrict__ x, const float* __restrict__ wbar,
                              int* __restrict__ sgn, int* __restrict__ poslist,
                              int* __restrict__ neglist, int* __restrict__ counts,
                              int rows, int D) {
    int warp = threadIdx.x >> 5, lane = threadIdx.x & 31;
    int rn = blockIdx.x * 8 + warp;
    if (rn >= rows) return;
    const float* row = x + (size_t)rn * D;
    float s = 0.f;
    for (int j = lane * 4; j < D; j += 128) {
        float4 v = *(const float4*)(row + j);
        float4 w = *(const float4*)(wbar + j);
        s += v.x * w.x + v.y * w.y + v.z * w.z + v.w * w.w;
    }
    #pragma unroll
    for (int off = 16; off; off >>= 1) s += __shfl_xor_sync(0xffffffffu, s, off);
    if (lane == 0) {
        int sg = (s >= 0.f) ? 1 : 0;
        sgn[rn] = sg;
        if (sg) { int slot = atomicAdd(&counts[0], 1); poslist[slot] = rn; }
        else    { int slot = atomicAdd(&counts[1], 1); neglist[slot] = rn; }
    }
}

// ---------------------------------------------------------------------------
// topk: 2-stage bitonic. key = (orderable(value) << 32) | ~idx
// ---------------------------------------------------------------------------
__device__ __forceinline__ void bitonic_desc_1024(unsigned long long* s, int tid) {
    for (int k = 2; k <= 1024; k <<= 1) {
        for (int j = k >> 1; j > 0; j >>= 1) {
            int l = tid ^ j;
            if (l > tid) {
                unsigned long long a = s[tid], b = s[l];
                bool desc = ((tid & k) == 0);
                bool sw = desc ? (a < b) : (a > b);
                if (sw) { s[tid] = b; s[l] = a; }
            }
            __syncthreads();
        }
    }
}

__global__ void topk_stage1(const float* __restrict__ r, int M,
                            unsigned long long* __restrict__ cand) {
    int mode = blockIdx.y, seg = blockIdx.x, tid = threadIdx.x;
    __shared__ unsigned long long s[1024];
    int gi = seg * 1024 + tid;
    unsigned long long key = 0ull;
    if (gi < M) {
        uint32_t b = __float_as_uint(r[gi]);
        uint32_t u = (b & 0x80000000u) ? ~b : (b | 0x80000000u);
        if (mode) u = ~u;
        key = ((unsigned long long)u << 32) | (uint32_t)(~gi);
    }
    s[tid] = key;
    __syncthreads();
    bitonic_desc_1024(s, tid);
    if (tid < 32) cand[mode * 1024 + seg * 32 + tid] = s[tid];
}

__global__ void topk_stage2(const unsigned long long* __restrict__ cand, int ncand,
                            int* __restrict__ pos, int* __restrict__ neg) {
    int mode = blockIdx.x, tid = threadIdx.x;
    __shared__ unsigned long long s[1024];
    s[tid] = (tid < ncand) ? cand[mode * 1024 + tid] : 0ull;
    __syncthreads();
    bitonic_desc_1024(s, tid);
    if (tid < 32) {
        int idx = (int)(~(uint32_t)(s[tid] & 0xffffffffu));
        (mode ? neg : pos)[tid] = idx;
    }
}

// ---------------------------------------------------------------------------
// projections (fp32, small): out[slot,o] = sum_d src[idx[slot],d] * W[o,d]
// ---------------------------------------------------------------------------
__global__ void __launch_bounds__(256) proj_kernel(
        const float* __restrict__ mk, const float* __restrict__ mv,
        const float* __restrict__ Wk, const float* __restrict__ Wv,
        const int* __restrict__ pos, const int* __restrict__ neg,
        float* __restrict__ Kp, float* __restrict__ Kn,
        float* __restrict__ Vp, float* __restrict__ Vn, int D) {
    int mat = blockIdx.y;
    const float* src = (mat < 2) ? mk : mv;
    const float* W   = (mat < 2) ? Wk : Wv;
    const int*   idx = (mat & 1) ? neg : pos;
    float* outm = (mat == 0) ? Kp : (mat == 1) ? Kn : (mat == 2) ? Vp : Vn;

    int o0 = blockIdx.x * 128;
    __shared__ float Ks[32][36];
    __shared__ float Ws[32][132];
    __shared__ int   sidx[32];
    int tid = threadIdx.x;
    if (tid < 32) sidx[tid] = idx[tid];
    __syncthreads();

    int tx = tid & 31, ty = tid >> 5;
    float acc[4][4] = {};
    for (int k0 = 0; k0 < D; k0 += 32) {
        {
            int slot = tid >> 3; int d4 = (tid & 7) * 4;
            float4 v = *(const float4*)(src + (size_t)sidx[slot] * D + k0 + d4);
            Ks[d4 + 0][slot] = v.x; Ks[d4 + 1][slot] = v.y;
            Ks[d4 + 2][slot] = v.z; Ks[d4 + 3][slot] = v.w;
        }
        #pragma unroll
        for (int q = 0; q < 4; q++) {
            int l = tid + q * 256; int row = l >> 3; int d4 = (l & 7) * 4;
            float4 v = *(const float4*)(W + (size_t)(o0 + row) * D + k0 + d4);
            Ws[d4 + 0][row] = v.x; Ws[d4 + 1][row] = v.y;
            Ws[d4 + 2][row] = v.z; Ws[d4 + 3][row] = v.w;
        }
        __syncthreads();
        #pragma unroll
        for (int kk = 0; kk < 32; kk++) {
            float a[4], b[4];
            #pragma unroll
            for (int i = 0; i < 4; i++) a[i] = Ks[kk][ty * 4 + i];
            #pragma unroll
            for (int j = 0; j < 4; j++) b[j] = Ws[kk][tx * 4 + j];
            #pragma unroll
            for (int i = 0; i < 4; i++)
                #pragma unroll
                for (int j = 0; j < 4; j++) acc[i][j] += a[i] * b[j];
        }
        __syncthreads();
    }
    #pragma unroll
    for (int i = 0; i < 4; i++)
        #pragma unroll
        for (int j = 0; j < 4; j++)
            outm[(size_t)(ty * 4 + i) * D + o0 + tx * 4 + j] = acc[i][j];
}

// ---------------------------------------------------------------------------
// HMMA bf16 split-precision GEMM, 3-stage cp.async pipeline.
// CTA tile 64x128, BK=32, 8 warps (2m x 4n -> 32x32 per warp), 2 CTAs/SM.
// ---------------------------------------------------------------------------
#define STR 80
#define OAhi 0
#define OAlo 5120
#define OBhi 10240
#define OBlo 20480
#define BUFB 30720
#define GEMM_DSMEM (3 * BUFB)

__global__ void __launch_bounds__(256, 2) gemm_hmma_kernel(
        const __nv_bfloat16* __restrict__ Ahi, const __nv_bfloat16* __restrict__ Alo,
        const __nv_bfloat16* __restrict__ Bhi, const __nv_bfloat16* __restrict__ Blo,
        const float* __restrict__ bias, float* __restrict__ C, int Kd, int Nc) {
    extern __shared__ __align__(16) uint8_t dsm[];
    int tid = threadIdx.x, wid = tid >> 5, lane = tid & 31;
    int m0g = blockIdx.y * 64, n0g = blockIdx.x * 128;
    int m0w = (wid & 1) * 32, n0w = (wid >> 1) * 32;
    uint32_t sbase = smem_u32(dsm);
    uint32_t a_off = (lane % 16) * STR + (lane / 16) * 16;
    uint32_t b_off = ((lane & 7) + ((lane >> 4) << 3)) * STR + ((lane >> 3) & 1) * 16;
    float acc[2][4][4] = {};

    int nchunk = Kd / 32;
    auto load_chunk = [&](int c, int sel) {
        uint32_t bb = sbase + sel * BUFB;
        int k0 = c * 32;
        {   // A: 64 rows x 4 segs = 256 pieces
            int row = tid >> 2, seg = tid & 3;
            uint32_t so = row * STR + seg * 16;
            size_t ga = (size_t)(m0g + row) * Kd + k0 + seg * 8;
            CP_ASYNC16(bb + OAhi + so, Ahi + ga);
            CP_ASYNC16(bb + OAlo + so, Alo + ga);
        }
        #pragma unroll
        for (int q = 0; q < 2; q++) {  // B: 128 rows x 4 segs = 512 pieces
            int p = tid + q * 256;
            int row = p >> 2, seg = p & 3;
            uint32_t so = row * STR + seg * 16;
            size_t gb = (size_t)(n0g + row) * Kd + k0 + seg * 8;
            CP_ASYNC16(bb + OBhi + so, Bhi + gb);
            CP_ASYNC16(bb + OBlo + so, Blo + gb);
        }
    };

    load_chunk(0, 0); CP_COMMIT();
    load_chunk(1, 1); CP_COMMIT();

    for (int c = 0; c < nchunk; c++) {
        CP_WAIT(1);
        __syncthreads();
        if (c + 2 < nchunk) load_chunk(c + 2, (c + 2) % 3);
        CP_COMMIT();

        uint32_t bb = sbase + (c % 3) * BUFB;
        #pragma unroll
        for (int ks = 0; ks < 2; ks++) {
            uint32_t ahi[2][4], alo[2][4], bhi[2][4], blo[2][4];
            #pragma unroll
            for (int mf = 0; mf < 2; mf++) {
                uint32_t aaddr = bb + OAhi + (m0w + mf * 16) * STR + ks * 32 + a_off;
                ldsm_x4(ahi[mf], aaddr);
                ldsm_x4(alo[mf], aaddr + (OAlo - OAhi));
            }
            #pragma unroll
            for (int ng = 0; ng < 2; ng++) {
                uint32_t baddr = bb + OBhi + (n0w + ng * 16) * STR + ks * 32 + b_off;
                ldsm_x4(bhi[ng], baddr);
                ldsm_x4(blo[ng], baddr + (OBlo - OBhi));
            }
            #pragma unroll
            for (int mf = 0; mf < 2; mf++)
                #pragma unroll
                for (int nf = 0; nf < 4; nf++)
                    mma_bf16(acc[mf][nf], ahi[mf], &bhi[nf >> 1][(nf & 1) * 2]);
            #pragma unroll
            for (int mf = 0; mf < 2; mf++)
                #pragma unroll
                for (int nf = 0; nf < 4; nf++)
                    mma_bf16(acc[mf][nf], ahi[mf], &blo[nf >> 1][(nf & 1) * 2]);
            #pragma unroll
            for (int mf = 0; mf < 2; mf++)
                #pragma unroll
                for (int nf = 0; nf < 4; nf++)
                    mma_bf16(acc[mf][nf], alo[mf], &bhi[nf >> 1][(nf & 1) * 2]);
        }
    }

    #pragma unroll
    for (int mf = 0; mf < 2; mf++)
        #pragma unroll
        for (int nf = 0; nf < 4; nf++) {
            int col = n0g + n0w + nf * 8 + (lane & 3) * 2;
            float b0 = bias ? bias[col]     : 0.f;
            float b1 = bias ? bias[col + 1] : 0.f;
            int r0 = m0g + m0w + mf * 16 + (lane >> 2);
            float2 v0 = {acc[mf][nf][0] + b0, acc[mf][nf][1] + b1};
            float2 v1 = {acc[mf][nf][2] + b0, acc[mf][nf][3] + b1};
            *(float2*)(C + (size_t)r0 * Nc + col)       = v0;
            *(float2*)(C + (size_t)(r0 + 8) * Nc + col) = v1;
        }
}

// ---------------------------------------------------------------------------
// attention: 8 same-sign rows per block (K/V traffic amortized 8x)
// dynamic smem: qs[8*D] + sc[8*512]
// ---------------------------------------------------------------------------
#define ATTN_SMEM (8 * D_MAX * 4 + 8 * NHEADS * TKK * 4)

__global__ void __launch_bounds__(256) attn_kernel(
        const float* __restrict__ qfull,
        const float* __restrict__ Kp, const float* __restrict__ Kn,
        const float* __restrict__ Vp, const float* __restrict__ Vn,
        const int* __restrict__ pos, const int* __restrict__ neg,
        const int* __restrict__ poslist, const int* __restrict__ neglist,
        const int* __restrict__ counts,
        __nv_bfloat16* __restrict__ ctxhi, __nv_bfloat16* __restrict__ ctxlo,
        float* __restrict__ avg_out, float* __restrict__ sel_out,
        int D, float scale) {
    extern __shared__ float adsm[];
    float* qs = adsm;             // 8 * D
    float* sc = adsm + 8 * D_MAX; // 8 * 512
    __shared__ int rowids[8];
    __shared__ int s_nr, s_sgn, s_base;

    int tid = threadIdx.x, warp = tid >> 5, lane = tid & 31;

    if (tid == 0) {
        int npos = counts[0], nneg = counts[1];
        int nbp = (npos + 7) >> 3;
        int b = blockIdx.x;
        int nr = 0, sg = 1, base = 0;
        if (b < nbp) {
            base = b * 8; nr = min(8, npos - base); sg = 1;
        } else {
            int b2 = b - nbp; base = b2 * 8;
            if (base < nneg) { nr = min(8, nneg - base); sg = 0; }
        }
        s_nr = nr; s_sgn = sg; s_base = base;
    }
    __syncthreads();
    int nr = s_nr;
    if (nr == 0) return;
    int sg = s_sgn;
    const float* Km = sg ? Kp : Kn;
    const float* Vm = sg ? Vp : Vn;
    const int* idx  = sg ? pos : neg;
    if (tid < nr) rowids[tid] = (sg ? poslist : neglist)[s_base + tid];
    __syncthreads();

    for (int r = 0; r < nr; r++)
        for (int j = tid * 4; j < D; j += 1024)
            *(float4*)(qs + r * D_MAX + j) =
                *(const float4*)(qfull + (size_t)rowids[r] * D + j);
    __syncthreads();

    // scores: 512 (h,k) pairs, 64/warp; K row loaded once, dotted vs nr rows
    for (int t = 0; t < 64; t++) {
        int p = warp * 64 + t;
        int h = p >> 5, k = p & 31;
        const float* kr = Km + (size_t)k * D + h * 64;
        float k0 = kr[lane], k1 = kr[lane + 32];
        #pragma unroll
        for (int r = 0; r < 8; r++) {
            if (r >= nr) break;
            const float* qr = qs + r * D_MAX + h * 64;
            float v = qr[lane] * k0 + qr[lane + 32] * k1;
            #pragma unroll
            for (int off = 16; off; off >>= 1) v += __shfl_xor_sync(0xffffffffu, v, off);
            if (lane == 0) sc[r * 512 + p] = v * scale;
        }
    }
    __syncthreads();

    // softmax per (r,h): nr*16 rows of 32
    for (int q = warp; q < nr * NHEADS; q += 8) {
        int r = q >> 4, h = q & 15;
        float v = sc[r * 512 + h * 32 + lane];
        float mx = v;
        #pragma unroll
        for (int off = 16; off; off >>= 1) mx = fmaxf(mx, __shfl_xor_sync(0xffffffffu, mx, off));
        float e = expf(v - mx);
        float s = e;
        #pragma unroll
        for (int off = 16; off; off >>= 1) s += __shfl_xor_sync(0xffffffffu, s, off);
        sc[r * 512 + h * 32 + lane] = e / s;
    }
    __syncthreads();

    if (tid < 32) {
        for (int r = 0; r < nr; r++) {
            int rn = rowids[r];
            if (avg_out) {
                float a = 0.f;
                #pragma unroll
                for (int h = 0; h < NHEADS; h++) a += sc[r * 512 + h * 32 + tid];
                avg_out[(size_t)rn * TKK + tid] = a * (1.f / NHEADS);
            }
            if (sel_out) sel_out[(size_t)rn * TKK + tid] = (float)idx[tid];
        }
    }

    // ctx: V element loaded once, used by nr rows
    for (int o = tid; o < D; o += 256) {
        int h = o >> 6;
        float a[8] = {};
        #pragma unroll
        for (int k = 0; k < TKK; k++) {
            float vv = Vm[(size_t)k * D + o];
            #pragma unroll
            for (int r = 0; r < 8; r++) {
                if (r >= nr) break;
                a[r] += sc[r * 512 + h * 32 + k] * vv;
            }
        }
        #pragma unroll
        for (int r = 0; r < 8; r++) {
            if (r >= nr) break;
            __nv_bfloat16 hi = __float2bfloat16(a[r]);
            __nv_bfloat16 lo = __float2bfloat16(a[r] - __bfloat162float(hi));
            size_t off = (size_t)rowids[r] * D + o;
            ctxhi[off] = hi;
            ctxlo[off] = lo;
        }
    }
}

// ---------------------------------------------------------------------------
// LayerNorm in-place per row
// ---------------------------------------------------------------------------
__global__ void __launch_bounds__(256) ln_kernel(
        float* __restrict__ out, const float* __restrict__ gamma,
        const float* __restrict__ beta, int D, float eps) {
    int rn = blockIdx.x;
    float* row = out + (size_t)rn * D;
    int tid = threadIdx.x;
    int warp = tid >> 5, lane = tid & 31;
    __shared__ float ssum[8], ssq[8];

    float s = 0.f, ss = 0.f;
    for (int j = tid * 4; j < D; j += 1024) {
        float4 v = *(const float4*)(row + j);
        s  += v.x + v.y + v.z + v.w;
        ss += v.x * v.x + v.y * v.y + v.z * v.z + v.w * v.w;
    }
    #pragma unroll
    for (int off = 16; off; off >>= 1) {
        s  += __shfl_xor_sync(0xffffffffu, s, off);
        ss += __shfl_xor_sync(0xffffffffu, ss, off);
    }
    if (lane == 0) { ssum[warp] = s; ssq[warp] = ss; }
    __syncthreads();
    if (tid == 0) {
        float ts = 0.f, tq = 0.f;
        #pragma unroll
        for (int w = 0; w < 8; w++) { ts += ssum[w]; tq += ssq[w]; }
        ssum[0] = ts; ssq[0] = tq;
    }
    __syncthreads();
    float mu = ssum[0] / D;
    float var = ssq[0] / D - mu * mu;
    float rstd = rsqrtf(var + eps);
    for (int j = tid * 4; j < D; j += 1024) {
        float4 v = *(const float4*)(row + j);
        float4 g = *(const float4*)(gamma + j);
        float4 bb = *(const float4*)(beta + j);
        v.x = (v.x - mu) * rstd * g.x + bb.x;
        v.y = (v.y - mu) * rstd * g.y + bb.y;
        v.z = (v.z - mu) * rstd * g.z + bb.z;
        v.w = (v.w - mu) * rstd * g.w + bb.w;
        *(float4*)(row + j) = v;
    }
}

// ---------------------------------------------------------------------------
// launch
// ---------------------------------------------------------------------------
extern "C" void kernel_launch(void* const* d_in, const int* in_sizes, int n_in,
                              void* d_out, int out_size) {
    const float* x     = (const float*)d_in[0];
    const float* mk    = (const float*)d_in[1];
    const float* mv    = (const float*)d_in[2];
    const float* Wq    = (const float*)d_in[3];
    const float* Wk    = (const float*)d_in[4];
    const float* Wv    = (const float*)d_in[5];
    const float* Wo    = (const float*)d_in[6];
    const float* bo    = (const float*)d_in[7];
    const float* gamma = (const float*)d_in[8];
    const float* beta  = (const float*)d_in[9];

    int D    = in_sizes[7];
    int rows = in_sizes[0] / D;           // B*N
    int M    = in_sizes[1] / D;
    int hd   = D / NHEADS;

    float* out = (float*)d_out;
    float* avg_out = nullptr;
    float* sel_out = nullptr;
    if ((long long)out_size >= (long long)rows * (D + 2 * TKK)) {
        avg_out = out + (size_t)rows * D;
        sel_out = avg_out + (size_t)rows * TKK;
    }

    float *p_r, *p_wbar, *p_part, *p_Kp, *p_Kn, *p_Vp, *p_Vn, *p_qf;
    int *p_pos, *p_neg, *p_sgn, *p_plist, *p_nlist, *p_cnt;
    unsigned long long* p_cand;
    __nv_bfloat16 *p_xhi, *p_xlo, *p_chi, *p_clo, *p_Wqhi, *p_Wqlo, *p_Wohi, *p_Wolo;
    cudaGetSymbolAddress((void**)&p_r,    g_r);
    cudaGetSymbolAddress((void**)&p_wbar, g_wbar);
    cudaGetSymbolAddress((void**)&p_part, g_colpart);
    cudaGetSymbolAddress((void**)&p_pos,  g_posidx);
    cudaGetSymbolAddress((void**)&p_neg,  g_negidx);
    cudaGetSymbolAddress((void**)&p_sgn,  g_sign);
    cudaGetSymbolAddress((void**)&p_plist, g_poslist);
    cudaGetSymbolAddress((void**)&p_nlist, g_neglist);
    cudaGetSymbolAddress((void**)&p_cnt,  g_counts);
    cudaGetSymbolAddress((void**)&p_cand, g_cand);
    cudaGetSymbolAddress((void**)&p_Kp,   g_Kp);
    cudaGetSymbolAddress((void**)&p_Kn,   g_Kn);
    cudaGetSymbolAddress((void**)&p_Vp,   g_Vp);
    cudaGetSymbolAddress((void**)&p_Vn,   g_Vn);
    cudaGetSymbolAddress((void**)&p_qf,   g_qfull);
    cudaGetSymbolAddress((void**)&p_xhi,  g_xhi);
    cudaGetSymbolAddress((void**)&p_xlo,  g_xlo);
    cudaGetSymbolAddress((void**)&p_chi,  g_ctxhi);
    cudaGetSymbolAddress((void**)&p_clo,  g_ctxlo);
    cudaGetSymbolAddress((void**)&p_Wqhi, g_Wqhi);
    cudaGetSymbolAddress((void**)&p_Wqlo, g_Wqlo);
    cudaGetSymbolAddress((void**)&p_Wohi, g_Wohi);
    cudaGetSymbolAddress((void**)&p_Wolo, g_Wolo);

    cudaFuncSetAttribute(gemm_hmma_kernel, cudaFuncAttributeMaxDynamicSharedMemorySize,
                         GEMM_DSMEM);
    cudaFuncSetAttribute(attn_kernel, cudaFuncAttributeMaxDynamicSharedMemorySize,
                         ATTN_SMEM);

    float sqrtD = sqrtf((float)D);
    float scale = 1.f / sqrtf((float)hd);

    int nx4 = rows * D / 4, nw4 = D * D / 4;
    // launches 1-3: splits; launch 4: gemm1 (ncu captures launch #4)
    split_kernel<<<(nx4 + 255) / 256, 256>>>(x,  p_xhi,  p_xlo,  nx4);
    split_kernel<<<(nw4 + 255) / 256, 256>>>(Wq, p_Wqhi, p_Wqlo, nw4);
    split_kernel<<<(nw4 + 255) / 256, 256>>>(Wo, p_Wohi, p_Wolo, nw4);

    gemm_hmma_kernel<<<dim3(D / 128, rows / 64), 256, GEMM_DSMEM>>>(
        p_xhi, p_xlo, p_Wqhi, p_Wqlo, nullptr, p_qf, D, D);

    zerocnt_kernel<<<1, 32>>>(p_cnt);
    colsum1_kernel<<<dim3((D + 255) / 256, 8), 256>>>(Wq, p_part, D);
    colsum2_kernel<<<(D + 255) / 256, 256>>>(p_part, p_wbar, D);
    rowstat_kernel<<<(M + 7) / 8, 256>>>(mk, p_r, M, D, sqrtD);
    qmsign_kernel<<<(rows + 7) / 8, 256>>>(x, p_wbar, p_sgn, p_plist, p_nlist, p_cnt,
                                           rows, D);

    int segs = (M + 1023) / 1024;
    topk_stage1<<<dim3(segs, 2), 1024>>>(p_r, M, p_cand);
    topk_stage2<<<2, 1024>>>(p_cand, segs * 32, p_pos, p_neg);

    proj_kernel<<<dim3(D / 128, 4), 256>>>(mk, mv, Wk, Wv, p_pos, p_neg,
                                           p_Kp, p_Kn, p_Vp, p_Vn, D);

    attn_kernel<<<rows / 8 + 2, 256, ATTN_SMEM>>>(
        p_qf, p_Kp, p_Kn, p_Vp, p_Vn, p_pos, p_neg, p_plist, p_nlist, p_cnt,
        p_chi, p_clo, avg_out, sel_out, D, scale);

    gemm_hmma_kernel<<<dim3(D / 128, rows / 64), 256, GEMM_DSMEM>>>(
        p_chi, p_clo, p_Wohi, p_Wolo, bo, out, D, D);

    ln_kernel<<<rows, 256>>>(out, gamma, beta, D, 1e-5f);
}

// round 8
// speedup vs baseline: 1.1582x; 1.1582x over previous
#include <cuda_runtime.h>
#include <cuda_bf16.h>
#include <math.h>
#include <stdint.h>

// ============================================================================
// CrossAttentionReader — GB300 sm_103a, round 8
//  - GEMM reverted to round-6 (best: 128x128, 512 thr, 3-stage)
//  - attn: 2 same-sign rows/block, 512 thr — same shfl-chain parallelism as
//    round 6, half the K/V L2 traffic
//  - rowstat at launch #4 for profiling visibility
// ============================================================================

#define D_MAX     1024
#define M_MAX     32768
#define ROWS_MAX  2048
#define TKK       32
#define NHEADS    16

// ---- scratch (device globals; no allocation allowed) ----
__device__ float g_r[M_MAX];
__device__ float g_wbar[D_MAX];
__device__ float g_colpart[8 * D_MAX];
__device__ int   g_posidx[TKK];
__device__ int   g_negidx[TKK];
__device__ int   g_sign[ROWS_MAX];
__device__ int   g_poslist[ROWS_MAX];
__device__ int   g_neglist[ROWS_MAX];
__device__ int   g_counts[2];
__device__ unsigned long long g_cand[2 * 1024];
__device__ float g_Kp[TKK * D_MAX];
__device__ float g_Kn[TKK * D_MAX];
__device__ float g_Vp[TKK * D_MAX];
__device__ float g_Vn[TKK * D_MAX];
__device__ float g_qfull[(size_t)ROWS_MAX * D_MAX];
__device__ __nv_bfloat16 g_xhi[(size_t)ROWS_MAX * D_MAX];
__device__ __nv_bfloat16 g_xlo[(size_t)ROWS_MAX * D_MAX];
__device__ __nv_bfloat16 g_ctxhi[(size_t)ROWS_MAX * D_MAX];
__device__ __nv_bfloat16 g_ctxlo[(size_t)ROWS_MAX * D_MAX];
__device__ __nv_bfloat16 g_Wqhi[(size_t)D_MAX * D_MAX];
__device__ __nv_bfloat16 g_Wqlo[(size_t)D_MAX * D_MAX];
__device__ __nv_bfloat16 g_Wohi[(size_t)D_MAX * D_MAX];
__device__ __nv_bfloat16 g_Wolo[(size_t)D_MAX * D_MAX];

// ============================ helpers ===================================
__device__ __forceinline__ uint32_t smem_u32(const void* p) {
    uint32_t a;
    asm("{ .reg .u64 t; cvta.to.shared.u64 t, %1; cvt.u32.u64 %0, t; }" : "=r"(a) : "l"(p));
    return a;
}
__device__ __forceinline__ void ldsm_x4(uint32_t* r, uint32_t addr) {
    asm volatile("ldmatrix.sync.aligned.m8n8.x4.shared.b16 {%0,%1,%2,%3}, [%4];"
                 : "=r"(r[0]), "=r"(r[1]), "=r"(r[2]), "=r"(r[3]) : "r"(addr));
}
__device__ __forceinline__ void mma_bf16(float* d, const uint32_t* a, const uint32_t* b) {
    asm volatile("mma.sync.aligned.m16n8k16.row.col.f32.bf16.bf16.f32 "
                 "{%0,%1,%2,%3}, {%4,%5,%6,%7}, {%8,%9}, {%0,%1,%2,%3};"
                 : "+f"(d[0]), "+f"(d[1]), "+f"(d[2]), "+f"(d[3])
                 : "r"(a[0]), "r"(a[1]), "r"(a[2]), "r"(a[3]), "r"(b[0]), "r"(b[1]));
}
#define CP_ASYNC16(sa, gp) \
    asm volatile("cp.async.cg.shared.global [%0], [%1], 16;" :: "r"(sa), "l"(gp))
#define CP_COMMIT() asm volatile("cp.async.commit_group;" ::: "memory")
#define CP_WAIT(n)  asm volatile("cp.async.wait_group %0;" :: "n"(n) : "memory")

// ---------------------------------------------------------------------------
// split fp32 -> bf16 hi/lo
// ---------------------------------------------------------------------------
__global__ void split_kernel(const float* __restrict__ src, __nv_bfloat16* __restrict__ hi,
                             __nv_bfloat16* __restrict__ lo, int n4) {
    int i = blockIdx.x * 256 + threadIdx.x;
    if (i >= n4) return;
    float4 v = ((const float4*)src)[i];
    __nv_bfloat16 h0 = __float2bfloat16(v.x), h1 = __float2bfloat16(v.y);
    __nv_bfloat16 h2 = __float2bfloat16(v.z), h3 = __float2bfloat16(v.w);
    __nv_bfloat16 l0 = __float2bfloat16(v.x - __bfloat162float(h0));
    __nv_bfloat16 l1 = __float2bfloat16(v.y - __bfloat162float(h1));
    __nv_bfloat16 l2 = __float2bfloat16(v.z - __bfloat162float(h2));
    __nv_bfloat16 l3 = __float2bfloat16(v.w - __bfloat162float(h3));
    ((__nv_bfloat162*)hi)[2 * i]     = __nv_bfloat162(h0, h1);
    ((__nv_bfloat162*)hi)[2 * i + 1] = __nv_bfloat162(h2, h3);
    ((__nv_bfloat162*)lo)[2 * i]     = __nv_bfloat162(l0, l1);
    ((__nv_bfloat162*)lo)[2 * i + 1] = __nv_bfloat162(l2, l3);
}

// ---------------------------------------------------------------------------
// zero the pos/neg counters (graph-replay safe)
// ---------------------------------------------------------------------------
__global__ void zerocnt_kernel(int* counts) {
    if (threadIdx.x < 2) counts[threadIdx.x] = 0;
}

// ---------------------------------------------------------------------------
// column sum of Wq — two-stage deterministic reduction
// ---------------------------------------------------------------------------
__global__ void colsum1_kernel(const float* __restrict__ W, float* __restrict__ part, int D) {
    int d = blockIdx.x * 256 + threadIdx.x;
    if (d >= D) return;
    int r0 = blockIdx.y * 128;
    float s = 0.f;
    for (int r = r0; r < r0 + 128; r++) s += W[(size_t)r * D + d];
    part[blockIdx.y * D + d] = s;
}
__global__ void colsum2_kernel(const float* __restrict__ part, float* __restrict__ wbar, int D) {
    int d = blockIdx.x * 256 + threadIdx.x;
    if (d >= D) return;
    float s = 0.f;
    #pragma unroll
    for (int i = 0; i < 8; i++) s += part[i * D + d];
    wbar[d] = s;
}

// ---------------------------------------------------------------------------
// per-row r[m] = sum / (sqrtD * norm)
// ---------------------------------------------------------------------------
__global__ void rowstat_kernel(const float* __restrict__ mk, float* __restrict__ r,
                               int M, int D, float sqrtD) {
    int warp = threadIdx.x >> 5, lane = threadIdx.x & 31;
    int m = blockIdx.x * 8 + warp;
    if (m >= M) return;
    const float* row = mk + (size_t)m * D;
    float s = 0.f, ss = 0.f;
    for (int j = lane * 4; j < D; j += 128) {
        float4 v = *(const float4*)(row + j);
        s  += v.x + v.y + v.z + v.w;
        ss += v.x * v.x + v.y * v.y + v.z * v.z + v.w * v.w;
    }
    #pragma unroll
    for (int off = 16; off; off >>= 1) {
        s  += __shfl_xor_sync(0xffffffffu, s, off);
        ss += __shfl_xor_sync(0xffffffffu, ss, off);
    }
    if (lane == 0) r[m] = s / (sqrtD * sqrtf(ss));
}

// ---------------------------------------------------------------------------
// sign(qm) per row; append row to pos/neg list (order-independent outputs)
// ---------------------------------------------------------------------------
__global__ void qmsign_kernel(const float* __restrict__ x, const float* __restrict__ wbar,
                              int* __restrict__ sgn, int* __restrict__ poslist,
                              int* __restrict__ neglist, int* __restrict__ counts,
                              int rows, int D) {
    int warp = threadIdx.x >> 5, lane = threadIdx.x & 31;
    int rn = blockIdx.x * 8 + warp;
    if (rn >= rows) return;
    const float* row = x + (size_t)rn * D;
    float s = 0.f;
    for (int j = lane * 4; j < D; j += 128) {
        float4 v = *(const float4*)(row + j);
        float4 w = *(const float4*)(wbar + j);
        s += v.x * w.x + v.y * w.y + v.z * w.z + v.w * w.w;
    }
    #pragma unroll
    for (int off = 16; off; off >>= 1) s += __shfl_xor_sync(0xffffffffu, s, off);
    if (lane == 0) {
        int sg = (s >= 0.f) ? 1 : 0;
        sgn[rn] = sg;
        if (sg) { int slot = atomicAdd(&counts[0], 1); poslist[slot] = rn; }
        else    { int slot = atomicAdd(&counts[1], 1); neglist[slot] = rn; }
    }
}

// ---------------------------------------------------------------------------
// topk: 2-stage bitonic. key = (orderable(value) << 32) | ~idx
// ---------------------------------------------------------------------------
__device__ __forceinline__ void bitonic_desc_1024(unsigned long long* s, int tid) {
    for (int k = 2; k <= 1024; k <<= 1) {
        for (int j = k >> 1; j > 0; j >>= 1) {
            int l = tid ^ j;
            if (l > tid) {
                unsigned long long a = s[tid], b = s[l];
                bool desc = ((tid & k) == 0);
                bool sw = desc ? (a < b) : (a > b);
                if (sw) { s[tid] = b; s[l] = a; }
            }
            __syncthreads();
        }
    }
}

__global__ void topk_stage1(const float* __restrict__ r, int M,
                            unsigned long long* __restrict__ cand) {
    int mode = blockIdx.y, seg = blockIdx.x, tid = threadIdx.x;
    __shared__ unsigned long long s[1024];
    int gi = seg * 1024 + tid;
    unsigned long long key = 0ull;
    if (gi < M) {
        uint32_t b = __float_as_uint(r[gi]);
        uint32_t u = (b & 0x80000000u) ? ~b : (b | 0x80000000u);
        if (mode) u = ~u;
        key = ((unsigned long long)u << 32) | (uint32_t)(~gi);
    }
    s[tid] = key;
    __syncthreads();
    bitonic_desc_1024(s, tid);
    if (tid < 32) cand[mode * 1024 + seg * 32 + tid] = s[tid];
}

__global__ void topk_stage2(const unsigned long long* __restrict__ cand, int ncand,
                            int* __restrict__ pos, int* __restrict__ neg) {
    int mode = blockIdx.x, tid = threadIdx.x;
    __shared__ unsigned long long s[1024];
    s[tid] = (tid < ncand) ? cand[mode * 1024 + tid] : 0ull;
    __syncthreads();
    bitonic_desc_1024(s, tid);
    if (tid < 32) {
        int idx = (int)(~(uint32_t)(s[tid] & 0xffffffffu));
        (mode ? neg : pos)[tid] = idx;
    }
}

// ---------------------------------------------------------------------------
// projections (fp32, small): out[slot,o] = sum_d src[idx[slot],d] * W[o,d]
// ---------------------------------------------------------------------------
__global__ void __launch_bounds__(256) proj_kernel(
        const float* __restrict__ mk, const float* __restrict__ mv,
        const float* __restrict__ Wk, const float* __restrict__ Wv,
        const int* __restrict__ pos, const int* __restrict__ neg,
        float* __restrict__ Kp, float* __restrict__ Kn,
        float* __restrict__ Vp, float* __restrict__ Vn, int D) {
    int mat = blockIdx.y;
    const float* src = (mat < 2) ? mk : mv;
    const float* W   = (mat < 2) ? Wk : Wv;
    const int*   idx = (mat & 1) ? neg : pos;
    float* outm = (mat == 0) ? Kp : (mat == 1) ? Kn : (mat == 2) ? Vp : Vn;

    int o0 = blockIdx.x * 128;
    __shared__ float Ks[32][36];
    __shared__ float Ws[32][132];
    __shared__ int   sidx[32];
    int tid = threadIdx.x;
    if (tid < 32) sidx[tid] = idx[tid];
    __syncthreads();

    int tx = tid & 31, ty = tid >> 5;
    float acc[4][4] = {};
    for (int k0 = 0; k0 < D; k0 += 32) {
        {
            int slot = tid >> 3; int d4 = (tid & 7) * 4;
            float4 v = *(const float4*)(src + (size_t)sidx[slot] * D + k0 + d4);
            Ks[d4 + 0][slot] = v.x; Ks[d4 + 1][slot] = v.y;
            Ks[d4 + 2][slot] = v.z; Ks[d4 + 3][slot] = v.w;
        }
        #pragma unroll
        for (int q = 0; q < 4; q++) {
            int l = tid + q * 256; int row = l >> 3; int d4 = (l & 7) * 4;
            float4 v = *(const float4*)(W + (size_t)(o0 + row) * D + k0 + d4);
            Ws[d4 + 0][row] = v.x; Ws[d4 + 1][row] = v.y;
            Ws[d4 + 2][row] = v.z; Ws[d4 + 3][row] = v.w;
        }
        __syncthreads();
        #pragma unroll
        for (int kk = 0; kk < 32; kk++) {
            float a[4], b[4];
            #pragma unroll
            for (int i = 0; i < 4; i++) a[i] = Ks[kk][ty * 4 + i];
            #pragma unroll
            for (int j = 0; j < 4; j++) b[j] = Ws[kk][tx * 4 + j];
            #pragma unroll
            for (int i = 0; i < 4; i++)
                #pragma unroll
                for (int j = 0; j < 4; j++) acc[i][j] += a[i] * b[j];
        }
        __syncthreads();
    }
    #pragma unroll
    for (int i = 0; i < 4; i++)
        #pragma unroll
        for (int j = 0; j < 4; j++)
            outm[(size_t)(ty * 4 + i) * D + o0 + tx * 4 + j] = acc[i][j];
}

// ---------------------------------------------------------------------------
// HMMA bf16 split-precision GEMM (round-6 best config).
// CTA tile 128x128, BK=32, 16 warps (4m x 4n -> 32x32 per warp), 3-stage.
// ---------------------------------------------------------------------------
#define STR 80
#define OAhi 0
#define OAlo 10240
#define OBhi 20480
#define OBlo 30720
#define BUFB 40960
#define GEMM_DSMEM (3 * BUFB)

__global__ void __launch_bounds__(512) gemm_hmma_kernel(
        const __nv_bfloat16* __restrict__ Ahi, const __nv_bfloat16* __restrict__ Alo,
        const __nv_bfloat16* __restrict__ Bhi, const __nv_bfloat16* __restrict__ Blo,
        const float* __restrict__ bias, float* __restrict__ C, int Kd, int Nc) {
    extern __shared__ __align__(16) uint8_t dsm[];
    int tid = threadIdx.x, wid = tid >> 5, lane = tid & 31;
    int m0g = blockIdx.y * 128, n0g = blockIdx.x * 128;
    int m0w = (wid & 3) * 32, n0w = (wid >> 2) * 32;
    uint32_t sbase = smem_u32(dsm);
    uint32_t a_off = (lane % 16) * STR + (lane / 16) * 16;
    uint32_t b_off = ((lane & 7) + ((lane >> 4) << 3)) * STR + ((lane >> 3) & 1) * 16;
    float acc[2][4][4] = {};

    int nchunk = Kd / 32;
    int lrow = tid >> 2, lseg = tid & 3;
    uint32_t lso = lrow * STR + lseg * 16;
    auto load_chunk = [&](int c, int sel) {
        uint32_t bb = sbase + sel * BUFB;
        int k0 = c * 32;
        size_t ga = (size_t)(m0g + lrow) * Kd + k0 + lseg * 8;
        size_t gb = (size_t)(n0g + lrow) * Kd + k0 + lseg * 8;
        CP_ASYNC16(bb + OAhi + lso, Ahi + ga);
        CP_ASYNC16(bb + OAlo + lso, Alo + ga);
        CP_ASYNC16(bb + OBhi + lso, Bhi + gb);
        CP_ASYNC16(bb + OBlo + lso, Blo + gb);
    };

    load_chunk(0, 0); CP_COMMIT();
    load_chunk(1, 1); CP_COMMIT();

    for (int c = 0; c < nchunk; c++) {
        CP_WAIT(1);
        __syncthreads();
        if (c + 2 < nchunk) load_chunk(c + 2, (c + 2) % 3);
        CP_COMMIT();

        uint32_t bb = sbase + (c % 3) * BUFB;
        #pragma unroll
        for (int ks = 0; ks < 2; ks++) {
            uint32_t ahi[2][4], alo[2][4], bhi[2][4], blo[2][4];
            #pragma unroll
            for (int mf = 0; mf < 2; mf++) {
                uint32_t aaddr = bb + OAhi + (m0w + mf * 16) * STR + ks * 32 + a_off;
                ldsm_x4(ahi[mf], aaddr);
                ldsm_x4(alo[mf], aaddr + (OAlo - OAhi));
            }
            #pragma unroll
            for (int ng = 0; ng < 2; ng++) {
                uint32_t baddr = bb + OBhi + (n0w + ng * 16) * STR + ks * 32 + b_off;
                ldsm_x4(bhi[ng], baddr);
                ldsm_x4(blo[ng], baddr + (OBlo - OBhi));
            }
            #pragma unroll
            for (int mf = 0; mf < 2; mf++)
                #pragma unroll
                for (int nf = 0; nf < 4; nf++)
                    mma_bf16(acc[mf][nf], ahi[mf], &bhi[nf >> 1][(nf & 1) * 2]);
            #pragma unroll
            for (int mf = 0; mf < 2; mf++)
                #pragma unroll
                for (int nf = 0; nf < 4; nf++)
                    mma_bf16(acc[mf][nf], ahi[mf], &blo[nf >> 1][(nf & 1) * 2]);
            #pragma unroll
            for (int mf = 0; mf < 2; mf++)
                #pragma unroll
                for (int nf = 0; nf < 4; nf++)
                    mma_bf16(acc[mf][nf], alo[mf], &bhi[nf >> 1][(nf & 1) * 2]);
        }
    }

    #pragma unroll
    for (int mf = 0; mf < 2; mf++)
        #pragma unroll
        for (int nf = 0; nf < 4; nf++) {
            int col = n0g + n0w + nf * 8 + (lane & 3) * 2;
            float b0 = bias ? bias[col]     : 0.f;
            float b1 = bias ? bias[col + 1] : 0.f;
            int r0 = m0g + m0w + mf * 16 + (lane >> 2);
            float2 v0 = {acc[mf][nf][0] + b0, acc[mf][nf][1] + b1};
            float2 v1 = {acc[mf][nf][2] + b0, acc[mf][nf][3] + b1};
            *(float2*)(C + (size_t)r0 * Nc + col)       = v0;
            *(float2*)(C + (size_t)(r0 + 8) * Nc + col) = v1;
        }
}

// ---------------------------------------------------------------------------
// attention: 2 same-sign rows per block, 512 threads (16 warps).
// Per-warp shuffle-chain count identical to the per-row version (64),
// total warp count identical; K/V L2 traffic halved.
// ---------------------------------------------------------------------------
__global__ void __launch_bounds__(512) attn_kernel(
        const float* __restrict__ qfull,
        const float* __restrict__ Kp, const float* __restrict__ Kn,
        const float* __restrict__ Vp, const float* __restrict__ Vn,
        const int* __restrict__ pos, const int* __restrict__ neg,
        const int* __restrict__ poslist, const int* __restrict__ neglist,
        const int* __restrict__ counts,
        __nv_bfloat16* __restrict__ ctxhi, __nv_bfloat16* __restrict__ ctxlo,
        float* __restrict__ avg_out, float* __restrict__ sel_out,
        int D, float scale) {
    __shared__ float qs[2 * D_MAX];
    __shared__ float sc[2 * NHEADS * TKK];
    __shared__ int rowids[2];
    __shared__ int s_nr, s_sgn;

    int tid = threadIdx.x, warp = tid >> 5, lane = tid & 31;

    if (tid == 0) {
        int npos = counts[0], nneg = counts[1];
        int nbp = (npos + 1) >> 1;
        int b = blockIdx.x;
        int nr = 0, sg = 1, base = 0;
        if (b < nbp) {
            base = b * 2; nr = min(2, npos - base); sg = 1;
        } else {
            int b2 = b - nbp; base = b2 * 2;
            if (base < nneg) { nr = min(2, nneg - base); sg = 0; }
        }
        s_nr = nr; s_sgn = sg;
        if (nr > 0) rowids[0] = (sg ? poslist : neglist)[base];
        if (nr > 1) rowids[1] = (sg ? poslist : neglist)[base + 1];
    }
    __syncthreads();
    int nr = s_nr;
    if (nr == 0) return;
    int sg = s_sgn;
    const float* Km = sg ? Kp : Kn;
    const float* Vm = sg ? Vp : Vn;
    const int* idx  = sg ? pos : neg;

    for (int r = 0; r < nr; r++)
        for (int j = tid * 4; j < D; j += 2048)
            *(float4*)(qs + r * D_MAX + j) =
                *(const float4*)(qfull + (size_t)rowids[r] * D + j);
    __syncthreads();

    // scores: warp -> (r = warp>>3, sub = warp&7); 64 reductions per warp
    {
        int r = warp >> 3, sub = warp & 7;
        if (r < nr) {
            const float* qbase = qs + r * D_MAX;
            for (int t = 0; t < 64; t++) {
                int p = sub * 64 + t;
                int h = p >> 5, k = p & 31;
                const float* kr = Km + (size_t)k * D + h * 64;
                const float* qr = qbase + h * 64;
                float v = qr[lane] * kr[lane] + qr[lane + 32] * kr[lane + 32];
                #pragma unroll
                for (int off = 16; off; off >>= 1) v += __shfl_xor_sync(0xffffffffu, v, off);
                if (lane == 0) sc[r * 512 + p] = v * scale;
            }
        }
    }
    __syncthreads();

    // softmax: 2 (r,h) pairs per warp
    #pragma unroll
    for (int qq = warp * 2; qq < warp * 2 + 2; qq++) {
        int r = qq >> 4, h = qq & 15;
        if (r < nr) {
            float v = sc[r * 512 + h * 32 + lane];
            float mx = v;
            #pragma unroll
            for (int off = 16; off; off >>= 1) mx = fmaxf(mx, __shfl_xor_sync(0xffffffffu, mx, off));
            float e = expf(v - mx);
            float s = e;
            #pragma unroll
            for (int off = 16; off; off >>= 1) s += __shfl_xor_sync(0xffffffffu, s, off);
            sc[r * 512 + h * 32 + lane] = e / s;
        }
    }
    __syncthreads();

    if (tid < 32) {
        for (int r = 0; r < nr; r++) {
            int rn = rowids[r];
            if (avg_out) {
                float a = 0.f;
                #pragma unroll
                for (int h = 0; h < NHEADS; h++) a += sc[r * 512 + h * 32 + tid];
                avg_out[(size_t)rn * TKK + tid] = a * (1.f / NHEADS);
            }
            if (sel_out) sel_out[(size_t)rn * TKK + tid] = (float)idx[tid];
        }
    }

    // ctx: V element loaded once, used for both rows
    for (int o = tid; o < D; o += 512) {
        int h = o >> 6;
        float a0 = 0.f, a1 = 0.f;
        const float* s0 = sc + h * 32;
        const float* s1 = sc + 512 + h * 32;
        #pragma unroll
        for (int k = 0; k < TKK; k++) {
            float vv = Vm[(size_t)k * D + o];
            a0 += s0[k] * vv;
            a1 += s1[k] * vv;
        }
        {
            __nv_bfloat16 hi = __float2bfloat16(a0);
            __nv_bfloat16 lo = __float2bfloat16(a0 - __bfloat162float(hi));
            size_t off = (size_t)rowids[0] * D + o;
            ctxhi[off] = hi; ctxlo[off] = lo;
        }
        if (nr > 1) {
            __nv_bfloat16 hi = __float2bfloat16(a1);
            __nv_bfloat16 lo = __float2bfloat16(a1 - __bfloat162float(hi));
            size_t off = (size_t)rowids[1] * D + o;
            ctxhi[off] = hi; ctxlo[off] = lo;
        }
    }
}

// ---------------------------------------------------------------------------
// LayerNorm in-place per row
// ---------------------------------------------------------------------------
__global__ void __launch_bounds__(256) ln_kernel(
        float* __restrict__ out, const float* __restrict__ gamma,
        const float* __restrict__ beta, int D, float eps) {
    int rn = blockIdx.x;
    float* row = out + (size_t)rn * D;
    int tid = threadIdx.x;
    int warp = tid >> 5, lane = tid & 31;
    __shared__ float ssum[8], ssq[8];

    float s = 0.f, ss = 0.f;
    for (int j = tid * 4; j < D; j += 1024) {
        float4 v = *(const float4*)(row + j);
        s  += v.x + v.y + v.z + v.w;
        ss += v.x * v.x + v.y * v.y + v.z * v.z + v.w * v.w;
    }
    #pragma unroll
    for (int off = 16; off; off >>= 1) {
        s  += __shfl_xor_sync(0xffffffffu, s, off);
        ss += __shfl_xor_sync(0xffffffffu, ss, off);
    }
    if (lane == 0) { ssum[warp] = s; ssq[warp] = ss; }
    __syncthreads();
    if (tid == 0) {
        float ts = 0.f, tq = 0.f;
        #pragma unroll
        for (int w = 0; w < 8; w++) { ts += ssum[w]; tq += ssq[w]; }
        ssum[0] = ts; ssq[0] = tq;
    }
    __syncthreads();
    float mu = ssum[0] / D;
    float var = ssq[0] / D - mu * mu;
    float rstd = rsqrtf(var + eps);
    for (int j = tid * 4; j < D; j += 1024) {
        float4 v = *(const float4*)(row + j);
        float4 g = *(const float4*)(gamma + j);
        float4 bb = *(const float4*)(beta + j);
        v.x = (v.x - mu) * rstd * g.x + bb.x;
        v.y = (v.y - mu) * rstd * g.y + bb.y;
        v.z = (v.z - mu) * rstd * g.z + bb.z;
        v.w = (v.w - mu) * rstd * g.w + bb.w;
        *(float4*)(row + j) = v;
    }
}

// ---------------------------------------------------------------------------
// launch
// ---------------------------------------------------------------------------
extern "C" void kernel_launch(void* const* d_in, const int* in_sizes, int n_in,
                              void* d_out, int out_size) {
    const float* x     = (const float*)d_in[0];
    const float* mk    = (const float*)d_in[1];
    const float* mv    = (const float*)d_in[2];
    const float* Wq    = (const float*)d_in[3];
    const float* Wk    = (const float*)d_in[4];
    const float* Wv    = (const float*)d_in[5];
    const float* Wo    = (const float*)d_in[6];
    const float* bo    = (const float*)d_in[7];
    const float* gamma = (const float*)d_in[8];
    const float* beta  = (const float*)d_in[9];

    int D    = in_sizes[7];
    int rows = in_sizes[0] / D;           // B*N
    int M    = in_sizes[1] / D;
    int hd   = D / NHEADS;

    float* out = (float*)d_out;
    float* avg_out = nullptr;
    float* sel_out = nullptr;
    if ((long long)out_size >= (long long)rows * (D + 2 * TKK)) {
        avg_out = out + (size_t)rows * D;
        sel_out = avg_out + (size_t)rows * TKK;
    }

    float *p_r, *p_wbar, *p_part, *p_Kp, *p_Kn, *p_Vp, *p_Vn, *p_qf;
    int *p_pos, *p_neg, *p_sgn, *p_plist, *p_nlist, *p_cnt;
    unsigned long long* p_cand;
    __nv_bfloat16 *p_xhi, *p_xlo, *p_chi, *p_clo, *p_Wqhi, *p_Wqlo, *p_Wohi, *p_Wolo;
    cudaGetSymbolAddress((void**)&p_r,    g_r);
    cudaGetSymbolAddress((void**)&p_wbar, g_wbar);
    cudaGetSymbolAddress((void**)&p_part, g_colpart);
    cudaGetSymbolAddress((void**)&p_pos,  g_posidx);
    cudaGetSymbolAddress((void**)&p_neg,  g_negidx);
    cudaGetSymbolAddress((void**)&p_sgn,  g_sign);
    cudaGetSymbolAddress((void**)&p_plist, g_poslist);
    cudaGetSymbolAddress((void**)&p_nlist, g_neglist);
    cudaGetSymbolAddress((void**)&p_cnt,  g_counts);
    cudaGetSymbolAddress((void**)&p_cand, g_cand);
    cudaGetSymbolAddress((void**)&p_Kp,   g_Kp);
    cudaGetSymbolAddress((void**)&p_Kn,   g_Kn);
    cudaGetSymbolAddress((void**)&p_Vp,   g_Vp);
    cudaGetSymbolAddress((void**)&p_Vn,   g_Vn);
    cudaGetSymbolAddress((void**)&p_qf,   g_qfull);
    cudaGetSymbolAddress((void**)&p_xhi,  g_xhi);
    cudaGetSymbolAddress((void**)&p_xlo,  g_xlo);
    cudaGetSymbolAddress((void**)&p_chi,  g_ctxhi);
    cudaGetSymbolAddress((void**)&p_clo,  g_ctxlo);
    cudaGetSymbolAddress((void**)&p_Wqhi, g_Wqhi);
    cudaGetSymbolAddress((void**)&p_Wqlo, g_Wqlo);
    cudaGetSymbolAddress((void**)&p_Wohi, g_Wohi);
    cudaGetSymbolAddress((void**)&p_Wolo, g_Wolo);

    cudaFuncSetAttribute(gemm_hmma_kernel, cudaFuncAttributeMaxDynamicSharedMemorySize,
                         GEMM_DSMEM);

    float sqrtD = sqrtf((float)D);
    float scale = 1.f / sqrtf((float)hd);

    int nx4 = rows * D / 4, nw4 = D * D / 4;
    // launches 1-3: splits; launch 4: rowstat (ncu captures launch #4)
    split_kernel<<<(nx4 + 255) / 256, 256>>>(x,  p_xhi,  p_xlo,  nx4);
    split_kernel<<<(nw4 + 255) / 256, 256>>>(Wq, p_Wqhi, p_Wqlo, nw4);
    split_kernel<<<(nw4 + 255) / 256, 256>>>(Wo, p_Wohi, p_Wolo, nw4);

    rowstat_kernel<<<(M + 7) / 8, 256>>>(mk, p_r, M, D, sqrtD);

    gemm_hmma_kernel<<<dim3(D / 128, rows / 128), 512, GEMM_DSMEM>>>(
        p_xhi, p_xlo, p_Wqhi, p_Wqlo, nullptr, p_qf, D, D);

    zerocnt_kernel<<<1, 32>>>(p_cnt);
    colsum1_kernel<<<dim3((D + 255) / 256, 8), 256>>>(Wq, p_part, D);
    colsum2_kernel<<<(D + 255) / 256, 256>>>(p_part, p_wbar, D);
    qmsign_kernel<<<(rows + 7) / 8, 256>>>(x, p_wbar, p_sgn, p_plist, p_nlist, p_cnt,
                                           rows, D);

    int segs = (M + 1023) / 1024;
    topk_stage1<<<dim3(segs, 2), 1024>>>(p_r, M, p_cand);
    topk_stage2<<<2, 1024>>>(p_cand, segs * 32, p_pos, p_neg);

    proj_kernel<<<dim3(D / 128, 4), 256>>>(mk, mv, Wk, Wv, p_pos, p_neg,
                                           p_Kp, p_Kn, p_Vp, p_Vn, D);

    attn_kernel<<<rows / 2 + 2, 512>>>(
        p_qf, p_Kp, p_Kn, p_Vp, p_Vn, p_pos, p_neg, p_plist, p_nlist, p_cnt,
        p_chi, p_clo, avg_out, sel_out, D, scale);

    gemm_hmma_kernel<<<dim3(D / 128, rows / 128), 512, GEMM_DSMEM>>>(
        p_chi, p_clo, p_Wohi, p_Wolo, bo, out, D, D);

    ln_kernel<<<rows, 256>>>(out, gamma, beta, D, 1e-5f);
}

// round 9
// speedup vs baseline: 1.2834x; 1.1081x over previous
#include <cuda_runtime.h>
#include <cuda_bf16.h>
#include <math.h>
#include <stdint.h>

// ============================================================================
// CrossAttentionReader — GB300 sm_103a, round 9
//  - kernels: exact round-6 set (best measured: 292.6us)
//  - NEW: graph fork — side branches (rowstat/topk/proj and colsum/qmsign)
//    run concurrently with splits+gemm1 via event fork/join during capture
// ============================================================================

#define D_MAX     1024
#define M_MAX     32768
#define ROWS_MAX  2048
#define TKK       32
#define NHEADS    16

// ---- scratch (device globals; no allocation allowed) ----
__device__ float g_r[M_MAX];
__device__ float g_wbar[D_MAX];
__device__ float g_colpart[8 * D_MAX];
__device__ int   g_posidx[TKK];
__device__ int   g_negidx[TKK];
__device__ int   g_sign[ROWS_MAX];
__device__ unsigned long long g_cand[2 * 1024];
__device__ float g_Kp[TKK * D_MAX];
__device__ float g_Kn[TKK * D_MAX];
__device__ float g_Vp[TKK * D_MAX];
__device__ float g_Vn[TKK * D_MAX];
__device__ float g_qfull[(size_t)ROWS_MAX * D_MAX];
__device__ __nv_bfloat16 g_xhi[(size_t)ROWS_MAX * D_MAX];
__device__ __nv_bfloat16 g_xlo[(size_t)ROWS_MAX * D_MAX];
__device__ __nv_bfloat16 g_ctxhi[(size_t)ROWS_MAX * D_MAX];
__device__ __nv_bfloat16 g_ctxlo[(size_t)ROWS_MAX * D_MAX];
__device__ __nv_bfloat16 g_Wqhi[(size_t)D_MAX * D_MAX];
__device__ __nv_bfloat16 g_Wqlo[(size_t)D_MAX * D_MAX];
__device__ __nv_bfloat16 g_Wohi[(size_t)D_MAX * D_MAX];
__device__ __nv_bfloat16 g_Wolo[(size_t)D_MAX * D_MAX];

// ============================ helpers ===================================
__device__ __forceinline__ uint32_t smem_u32(const void* p) {
    uint32_t a;
    asm("{ .reg .u64 t; cvta.to.shared.u64 t, %1; cvt.u32.u64 %0, t; }" : "=r"(a) : "l"(p));
    return a;
}
__device__ __forceinline__ void ldsm_x4(uint32_t* r, uint32_t addr) {
    asm volatile("ldmatrix.sync.aligned.m8n8.x4.shared.b16 {%0,%1,%2,%3}, [%4];"
                 : "=r"(r[0]), "=r"(r[1]), "=r"(r[2]), "=r"(r[3]) : "r"(addr));
}
__device__ __forceinline__ void mma_bf16(float* d, const uint32_t* a, const uint32_t* b) {
    asm volatile("mma.sync.aligned.m16n8k16.row.col.f32.bf16.bf16.f32 "
                 "{%0,%1,%2,%3}, {%4,%5,%6,%7}, {%8,%9}, {%0,%1,%2,%3};"
                 : "+f"(d[0]), "+f"(d[1]), "+f"(d[2]), "+f"(d[3])
                 : "r"(a[0]), "r"(a[1]), "r"(a[2]), "r"(a[3]), "r"(b[0]), "r"(b[1]));
}
#define CP_ASYNC16(sa, gp) \
    asm volatile("cp.async.cg.shared.global [%0], [%1], 16;" :: "r"(sa), "l"(gp))
#define CP_COMMIT() asm volatile("cp.async.commit_group;" ::: "memory")
#define CP_WAIT(n)  asm volatile("cp.async.wait_group %0;" :: "n"(n) : "memory")

// ---------------------------------------------------------------------------
// split fp32 -> bf16 hi/lo
// ---------------------------------------------------------------------------
__global__ void split_kernel(const float* __restrict__ src, __nv_bfloat16* __restrict__ hi,
                             __nv_bfloat16* __restrict__ lo, int n4) {
    int i = blockIdx.x * 256 + threadIdx.x;
    if (i >= n4) return;
    float4 v = ((const float4*)src)[i];
    __nv_bfloat16 h0 = __float2bfloat16(v.x), h1 = __float2bfloat16(v.y);
    __nv_bfloat16 h2 = __float2bfloat16(v.z), h3 = __float2bfloat16(v.w);
    __nv_bfloat16 l0 = __float2bfloat16(v.x - __bfloat162float(h0));
    __nv_bfloat16 l1 = __float2bfloat16(v.y - __bfloat162float(h1));
    __nv_bfloat16 l2 = __float2bfloat16(v.z - __bfloat162float(h2));
    __nv_bfloat16 l3 = __float2bfloat16(v.w - __bfloat162float(h3));
    ((__nv_bfloat162*)hi)[2 * i]     = __nv_bfloat162(h0, h1);
    ((__nv_bfloat162*)hi)[2 * i + 1] = __nv_bfloat162(h2, h3);
    ((__nv_bfloat162*)lo)[2 * i]     = __nv_bfloat162(l0, l1);
    ((__nv_bfloat162*)lo)[2 * i + 1] = __nv_bfloat162(l2, l3);
}

// ---------------------------------------------------------------------------
// column sum of Wq — two-stage deterministic reduction
// ---------------------------------------------------------------------------
__global__ void colsum1_kernel(const float* __restrict__ W, float* __restrict__ part, int D) {
    int d = blockIdx.x * 256 + threadIdx.x;
    if (d >= D) return;
    int r0 = blockIdx.y * 128;
    float s = 0.f;
    for (int r = r0; r < r0 + 128; r++) s += W[(size_t)r * D + d];
    part[blockIdx.y * D + d] = s;
}
__global__ void colsum2_kernel(const float* __restrict__ part, float* __restrict__ wbar, int D) {
    int d = blockIdx.x * 256 + threadIdx.x;
    if (d >= D) return;
    float s = 0.f;
    #pragma unroll
    for (int i = 0; i < 8; i++) s += part[i * D + d];
    wbar[d] = s;
}

// ---------------------------------------------------------------------------
// per-row r[m] = sum / (sqrtD * norm)
// ---------------------------------------------------------------------------
__global__ void rowstat_kernel(const float* __restrict__ mk, float* __restrict__ r,
                               int M, int D, float sqrtD) {
    int warp = threadIdx.x >> 5, lane = threadIdx.x & 31;
    int m = blockIdx.x * 8 + warp;
    if (m >= M) return;
    const float* row = mk + (size_t)m * D;
    float s = 0.f, ss = 0.f;
    for (int j = lane * 4; j < D; j += 128) {
        float4 v = *(const float4*)(row + j);
        s  += v.x + v.y + v.z + v.w;
        ss += v.x * v.x + v.y * v.y + v.z * v.z + v.w * v.w;
    }
    #pragma unroll
    for (int off = 16; off; off >>= 1) {
        s  += __shfl_xor_sync(0xffffffffu, s, off);
        ss += __shfl_xor_sync(0xffffffffu, ss, off);
    }
    if (lane == 0) r[m] = s / (sqrtD * sqrtf(ss));
}

// ---------------------------------------------------------------------------
// sign(qm) per row
// ---------------------------------------------------------------------------
__global__ void qmsign_kernel(const float* __restrict__ x, const float* __restrict__ wbar,
                              int* __restrict__ sgn, int rows, int D) {
    int warp = threadIdx.x >> 5, lane = threadIdx.x & 31;
    int rn = blockIdx.x * 8 + warp;
    if (rn >= rows) return;
    const float* row = x + (size_t)rn * D;
    float s = 0.f;
    for (int j = lane * 4; j < D; j += 128) {
        float4 v = *(const float4*)(row + j);
        float4 w = *(const float4*)(wbar + j);
        s += v.x * w.x + v.y * w.y + v.z * w.z + v.w * w.w;
    }
    #pragma unroll
    for (int off = 16; off; off >>= 1) s += __shfl_xor_sync(0xffffffffu, s, off);
    if (lane == 0) sgn[rn] = (s >= 0.f) ? 1 : 0;
}

// ---------------------------------------------------------------------------
// topk: 2-stage bitonic. key = (orderable(value) << 32) | ~idx
// ---------------------------------------------------------------------------
__device__ __forceinline__ void bitonic_desc_1024(unsigned long long* s, int tid) {
    for (int k = 2; k <= 1024; k <<= 1) {
        for (int j = k >> 1; j > 0; j >>= 1) {
            int l = tid ^ j;
            if (l > tid) {
                unsigned long long a = s[tid], b = s[l];
                bool desc = ((tid & k) == 0);
                bool sw = desc ? (a < b) : (a > b);
                if (sw) { s[tid] = b; s[l] = a; }
            }
            __syncthreads();
        }
    }
}

__global__ void topk_stage1(const float* __restrict__ r, int M,
                            unsigned long long* __restrict__ cand) {
    int mode = blockIdx.y, seg = blockIdx.x, tid = threadIdx.x;
    __shared__ unsigned long long s[1024];
    int gi = seg * 1024 + tid;
    unsigned long long key = 0ull;
    if (gi < M) {
        uint32_t b = __float_as_uint(r[gi]);
        uint32_t u = (b & 0x80000000u) ? ~b : (b | 0x80000000u);
        if (mode) u = ~u;
        key = ((unsigned long long)u << 32) | (uint32_t)(~gi);
    }
    s[tid] = key;
    __syncthreads();
    bitonic_desc_1024(s, tid);
    if (tid < 32) cand[mode * 1024 + seg * 32 + tid] = s[tid];
}

__global__ void topk_stage2(const unsigned long long* __restrict__ cand, int ncand,
                            int* __restrict__ pos, int* __restrict__ neg) {
    int mode = blockIdx.x, tid = threadIdx.x;
    __shared__ unsigned long long s[1024];
    s[tid] = (tid < ncand) ? cand[mode * 1024 + tid] : 0ull;
    __syncthreads();
    bitonic_desc_1024(s, tid);
    if (tid < 32) {
        int idx = (int)(~(uint32_t)(s[tid] & 0xffffffffu));
        (mode ? neg : pos)[tid] = idx;
    }
}

// ---------------------------------------------------------------------------
// projections (fp32, small): out[slot,o] = sum_d src[idx[slot],d] * W[o,d]
// ---------------------------------------------------------------------------
__global__ void __launch_bounds__(256) proj_kernel(
        const float* __restrict__ mk, const float* __restrict__ mv,
        const float* __restrict__ Wk, const float* __restrict__ Wv,
        const int* __restrict__ pos, const int* __restrict__ neg,
        float* __restrict__ Kp, float* __restrict__ Kn,
        float* __restrict__ Vp, float* __restrict__ Vn, int D) {
    int mat = blockIdx.y;
    const float* src = (mat < 2) ? mk : mv;
    const float* W   = (mat < 2) ? Wk : Wv;
    const int*   idx = (mat & 1) ? neg : pos;
    float* outm = (mat == 0) ? Kp : (mat == 1) ? Kn : (mat == 2) ? Vp : Vn;

    int o0 = blockIdx.x * 128;
    __shared__ float Ks[32][36];
    __shared__ float Ws[32][132];
    __shared__ int   sidx[32];
    int tid = threadIdx.x;
    if (tid < 32) sidx[tid] = idx[tid];
    __syncthreads();

    int tx = tid & 31, ty = tid >> 5;
    float acc[4][4] = {};
    for (int k0 = 0; k0 < D; k0 += 32) {
        {
            int slot = tid >> 3; int d4 = (tid & 7) * 4;
            float4 v = *(const float4*)(src + (size_t)sidx[slot] * D + k0 + d4);
            Ks[d4 + 0][slot] = v.x; Ks[d4 + 1][slot] = v.y;
            Ks[d4 + 2][slot] = v.z; Ks[d4 + 3][slot] = v.w;
        }
        #pragma unroll
        for (int q = 0; q < 4; q++) {
            int l = tid + q * 256; int row = l >> 3; int d4 = (l & 7) * 4;
            float4 v = *(const float4*)(W + (size_t)(o0 + row) * D + k0 + d4);
            Ws[d4 + 0][row] = v.x; Ws[d4 + 1][row] = v.y;
            Ws[d4 + 2][row] = v.z; Ws[d4 + 3][row] = v.w;
        }
        __syncthreads();
        #pragma unroll
        for (int kk = 0; kk < 32; kk++) {
            float a[4], b[4];
            #pragma unroll
            for (int i = 0; i < 4; i++) a[i] = Ks[kk][ty * 4 + i];
            #pragma unroll
            for (int j = 0; j < 4; j++) b[j] = Ws[kk][tx * 4 + j];
            #pragma unroll
            for (int i = 0; i < 4; i++)
                #pragma unroll
                for (int j = 0; j < 4; j++) acc[i][j] += a[i] * b[j];
        }
        __syncthreads();
    }
    #pragma unroll
    for (int i = 0; i < 4; i++)
        #pragma unroll
        for (int j = 0; j < 4; j++)
            outm[(size_t)(ty * 4 + i) * D + o0 + tx * 4 + j] = acc[i][j];
}

// ---------------------------------------------------------------------------
// HMMA bf16 split-precision GEMM (round-6 best config).
// CTA tile 128x128, BK=32, 16 warps (4m x 4n -> 32x32 per warp), 3-stage.
// ---------------------------------------------------------------------------
#define STR 80
#define OAhi 0
#define OAlo 10240
#define OBhi 20480
#define OBlo 30720
#define BUFB 40960
#define GEMM_DSMEM (3 * BUFB)

__global__ void __launch_bounds__(512) gemm_hmma_kernel(
        const __nv_bfloat16* __restrict__ Ahi, const __nv_bfloat16* __restrict__ Alo,
        const __nv_bfloat16* __restrict__ Bhi, const __nv_bfloat16* __restrict__ Blo,
        const float* __restrict__ bias, float* __restrict__ C, int Kd, int Nc) {
    extern __shared__ __align__(16) uint8_t dsm[];
    int tid = threadIdx.x, wid = tid >> 5, lane = tid & 31;
    int m0g = blockIdx.y * 128, n0g = blockIdx.x * 128;
    int m0w = (wid & 3) * 32, n0w = (wid >> 2) * 32;
    uint32_t sbase = smem_u32(dsm);
    uint32_t a_off = (lane % 16) * STR + (lane / 16) * 16;
    uint32_t b_off = ((lane & 7) + ((lane >> 4) << 3)) * STR + ((lane >> 3) & 1) * 16;
    float acc[2][4][4] = {};

    int nchunk = Kd / 32;
    int lrow = tid >> 2, lseg = tid & 3;
    uint32_t lso = lrow * STR + lseg * 16;
    auto load_chunk = [&](int c, int sel) {
        uint32_t bb = sbase + sel * BUFB;
        int k0 = c * 32;
        size_t ga = (size_t)(m0g + lrow) * Kd + k0 + lseg * 8;
        size_t gb = (size_t)(n0g + lrow) * Kd + k0 + lseg * 8;
        CP_ASYNC16(bb + OAhi + lso, Ahi + ga);
        CP_ASYNC16(bb + OAlo + lso, Alo + ga);
        CP_ASYNC16(bb + OBhi + lso, Bhi + gb);
        CP_ASYNC16(bb + OBlo + lso, Blo + gb);
    };

    load_chunk(0, 0); CP_COMMIT();
    load_chunk(1, 1); CP_COMMIT();

    for (int c = 0; c < nchunk; c++) {
        CP_WAIT(1);
        __syncthreads();
        if (c + 2 < nchunk) load_chunk(c + 2, (c + 2) % 3);
        CP_COMMIT();

        uint32_t bb = sbase + (c % 3) * BUFB;
        #pragma unroll
        for (int ks = 0; ks < 2; ks++) {
            uint32_t ahi[2][4], alo[2][4], bhi[2][4], blo[2][4];
            #pragma unroll
            for (int mf = 0; mf < 2; mf++) {
                uint32_t aaddr = bb + OAhi + (m0w + mf * 16) * STR + ks * 32 + a_off;
                ldsm_x4(ahi[mf], aaddr);
                ldsm_x4(alo[mf], aaddr + (OAlo - OAhi));
            }
            #pragma unroll
            for (int ng = 0; ng < 2; ng++) {
                uint32_t baddr = bb + OBhi + (n0w + ng * 16) * STR + ks * 32 + b_off;
                ldsm_x4(bhi[ng], baddr);
                ldsm_x4(blo[ng], baddr + (OBlo - OBhi));
            }
            #pragma unroll
            for (int mf = 0; mf < 2; mf++)
                #pragma unroll
                for (int nf = 0; nf < 4; nf++)
                    mma_bf16(acc[mf][nf], ahi[mf], &bhi[nf >> 1][(nf & 1) * 2]);
            #pragma unroll
            for (int mf = 0; mf < 2; mf++)
                #pragma unroll
                for (int nf = 0; nf < 4; nf++)
                    mma_bf16(acc[mf][nf], ahi[mf], &blo[nf >> 1][(nf & 1) * 2]);
            #pragma unroll
            for (int mf = 0; mf < 2; mf++)
                #pragma unroll
                for (int nf = 0; nf < 4; nf++)
                    mma_bf16(acc[mf][nf], alo[mf], &bhi[nf >> 1][(nf & 1) * 2]);
        }
    }

    #pragma unroll
    for (int mf = 0; mf < 2; mf++)
        #pragma unroll
        for (int nf = 0; nf < 4; nf++) {
            int col = n0g + n0w + nf * 8 + (lane & 3) * 2;
            float b0 = bias ? bias[col]     : 0.f;
            float b1 = bias ? bias[col + 1] : 0.f;
            int r0 = m0g + m0w + mf * 16 + (lane >> 2);
            float2 v0 = {acc[mf][nf][0] + b0, acc[mf][nf][1] + b1};
            float2 v1 = {acc[mf][nf][2] + b0, acc[mf][nf][3] + b1};
            *(float2*)(C + (size_t)r0 * Nc + col)       = v0;
            *(float2*)(C + (size_t)(r0 + 8) * Nc + col) = v1;
        }
}

// ---------------------------------------------------------------------------
// per-row attention (round-6 best); ctx emitted as bf16 hi/lo split
// ---------------------------------------------------------------------------
__global__ void __launch_bounds__(256) attn_kernel(
        const float* __restrict__ qfull,
        const float* __restrict__ Kp, const float* __restrict__ Kn,
        const float* __restrict__ Vp, const float* __restrict__ Vn,
        const int* __restrict__ pos, const int* __restrict__ neg,
        const int* __restrict__ sgn,
        __nv_bfloat16* __restrict__ ctxhi, __nv_bfloat16* __restrict__ ctxlo,
        float* __restrict__ avg_out, float* __restrict__ sel_out,
        int D, float scale) {
    int rn = blockIdx.x;
    int tid = threadIdx.x;
    int warp = tid >> 5, lane = tid & 31;
    __shared__ float qs[D_MAX];
    __shared__ float sc[NHEADS * TKK];

    int sg = sgn[rn];
    const float* Km = sg ? Kp : Kn;
    const float* Vm = sg ? Vp : Vn;
    const int* idx  = sg ? pos : neg;

    for (int j = tid * 4; j < D; j += 1024)
        *(float4*)(qs + j) = *(const float4*)(qfull + (size_t)rn * D + j);
    __syncthreads();

    for (int t = 0; t < 64; t++) {
        int p = warp * 64 + t;
        int h = p >> 5, k = p & 31;
        const float* kr = Km + (size_t)k * D + h * 64;
        const float* qr = qs + h * 64;
        float v = qr[lane] * kr[lane] + qr[lane + 32] * kr[lane + 32];
        #pragma unroll
        for (int off = 16; off; off >>= 1) v += __shfl_xor_sync(0xffffffffu, v, off);
        if (lane == 0) sc[p] = v * scale;
    }
    __syncthreads();

    #pragma unroll
    for (int hh = warp * 2; hh < warp * 2 + 2; hh++) {
        float v = sc[hh * 32 + lane];
        float mx = v;
        #pragma unroll
        for (int off = 16; off; off >>= 1) mx = fmaxf(mx, __shfl_xor_sync(0xffffffffu, mx, off));
        float e = expf(v - mx);
        float s = e;
        #pragma unroll
        for (int off = 16; off; off >>= 1) s += __shfl_xor_sync(0xffffffffu, s, off);
        sc[hh * 32 + lane] = e / s;
    }
    __syncthreads();

    if (tid < 32) {
        if (avg_out) {
            float a = 0.f;
            #pragma unroll
            for (int h = 0; h < NHEADS; h++) a += sc[h * 32 + tid];
            avg_out[(size_t)rn * TKK + tid] = a * (1.f / NHEADS);
        }
        if (sel_out) sel_out[(size_t)rn * TKK + tid] = (float)idx[tid];
    }

    for (int o = tid; o < D; o += 256) {
        int h = o >> 6;
        const float* arow = sc + h * 32;
        float a = 0.f;
        #pragma unroll
        for (int k = 0; k < TKK; k++) a += arow[k] * Vm[(size_t)k * D + o];
        __nv_bfloat16 hi = __float2bfloat16(a);
        __nv_bfloat16 lo = __float2bfloat16(a - __bfloat162float(hi));
        ctxhi[(size_t)rn * D + o] = hi;
        ctxlo[(size_t)rn * D + o] = lo;
    }
}

// ---------------------------------------------------------------------------
// LayerNorm in-place per row
// ---------------------------------------------------------------------------
__global__ void __launch_bounds__(256) ln_kernel(
        float* __restrict__ out, const float* __restrict__ gamma,
        const float* __restrict__ beta, int D, float eps) {
    int rn = blockIdx.x;
    float* row = out + (size_t)rn * D;
    int tid = threadIdx.x;
    int warp = tid >> 5, lane = tid & 31;
    __shared__ float ssum[8], ssq[8];

    float s = 0.f, ss = 0.f;
    for (int j = tid * 4; j < D; j += 1024) {
        float4 v = *(const float4*)(row + j);
        s  += v.x + v.y + v.z + v.w;
        ss += v.x * v.x + v.y * v.y + v.z * v.z + v.w * v.w;
    }
    #pragma unroll
    for (int off = 16; off; off >>= 1) {
        s  += __shfl_xor_sync(0xffffffffu, s, off);
        ss += __shfl_xor_sync(0xffffffffu, ss, off);
    }
    if (lane == 0) { ssum[warp] = s; ssq[warp] = ss; }
    __syncthreads();
    if (tid == 0) {
        float ts = 0.f, tq = 0.f;
        #pragma unroll
        for (int w = 0; w < 8; w++) { ts += ssum[w]; tq += ssq[w]; }
        ssum[0] = ts; ssq[0] = tq;
    }
    __syncthreads();
    float mu = ssum[0] / D;
    float var = ssq[0] / D - mu * mu;
    float rstd = rsqrtf(var + eps);
    for (int j = tid * 4; j < D; j += 1024) {
        float4 v = *(const float4*)(row + j);
        float4 g = *(const float4*)(gamma + j);
        float4 bb = *(const float4*)(beta + j);
        v.x = (v.x - mu) * rstd * g.x + bb.x;
        v.y = (v.y - mu) * rstd * g.y + bb.y;
        v.z = (v.z - mu) * rstd * g.z + bb.z;
        v.w = (v.w - mu) * rstd * g.w + bb.w;
        *(float4*)(row + j) = v;
    }
}

// ---------------------------------------------------------------------------
// launch — forked graph: side branches overlap splits+gemm1
// ---------------------------------------------------------------------------
extern "C" void kernel_launch(void* const* d_in, const int* in_sizes, int n_in,
                              void* d_out, int out_size) {
    const float* x     = (const float*)d_in[0];
    const float* mk    = (const float*)d_in[1];
    const float* mv    = (const float*)d_in[2];
    const float* Wq    = (const float*)d_in[3];
    const float* Wk    = (const float*)d_in[4];
    const float* Wv    = (const float*)d_in[5];
    const float* Wo    = (const float*)d_in[6];
    const float* bo    = (const float*)d_in[7];
    const float* gamma = (const float*)d_in[8];
    const float* beta  = (const float*)d_in[9];

    int D    = in_sizes[7];
    int rows = in_sizes[0] / D;           // B*N
    int M    = in_sizes[1] / D;
    int hd   = D / NHEADS;

    float* out = (float*)d_out;
    float* avg_out = nullptr;
    float* sel_out = nullptr;
    if ((long long)out_size >= (long long)rows * (D + 2 * TKK)) {
        avg_out = out + (size_t)rows * D;
        sel_out = avg_out + (size_t)rows * TKK;
    }

    float *p_r, *p_wbar, *p_part, *p_Kp, *p_Kn, *p_Vp, *p_Vn, *p_qf;
    int *p_pos, *p_neg, *p_sgn;
    unsigned long long* p_cand;
    __nv_bfloat16 *p_xhi, *p_xlo, *p_chi, *p_clo, *p_Wqhi, *p_Wqlo, *p_Wohi, *p_Wolo;
    cudaGetSymbolAddress((void**)&p_r,    g_r);
    cudaGetSymbolAddress((void**)&p_wbar, g_wbar);
    cudaGetSymbolAddress((void**)&p_part, g_colpart);
    cudaGetSymbolAddress((void**)&p_pos,  g_posidx);
    cudaGetSymbolAddress((void**)&p_neg,  g_negidx);
    cudaGetSymbolAddress((void**)&p_sgn,  g_sign);
    cudaGetSymbolAddress((void**)&p_cand, g_cand);
    cudaGetSymbolAddress((void**)&p_Kp,   g_Kp);
    cudaGetSymbolAddress((void**)&p_Kn,   g_Kn);
    cudaGetSymbolAddress((void**)&p_Vp,   g_Vp);
    cudaGetSymbolAddress((void**)&p_Vn,   g_Vn);
    cudaGetSymbolAddress((void**)&p_qf,   g_qfull);
    cudaGetSymbolAddress((void**)&p_xhi,  g_xhi);
    cudaGetSymbolAddress((void**)&p_xlo,  g_xlo);
    cudaGetSymbolAddress((void**)&p_chi,  g_ctxhi);
    cudaGetSymbolAddress((void**)&p_clo,  g_ctxlo);
    cudaGetSymbolAddress((void**)&p_Wqhi, g_Wqhi);
    cudaGetSymbolAddress((void**)&p_Wqlo, g_Wqlo);
    cudaGetSymbolAddress((void**)&p_Wohi, g_Wohi);
    cudaGetSymbolAddress((void**)&p_Wolo, g_Wolo);

    cudaFuncSetAttribute(gemm_hmma_kernel, cudaFuncAttributeMaxDynamicSharedMemorySize,
                         GEMM_DSMEM);

    // streams/events created once (first call runs outside graph capture);
    // no device memory involved — fork/join is graph-capture legal.
    static cudaStream_t sA = nullptr, sB = nullptr;
    static cudaEvent_t e0 = nullptr, e1 = nullptr, eA = nullptr, eB = nullptr;
    if (!sA) {
        cudaStreamCreateWithFlags(&sA, cudaStreamNonBlocking);
        cudaStreamCreateWithFlags(&sB, cudaStreamNonBlocking);
        cudaEventCreateWithFlags(&e0, cudaEventDisableTiming);
        cudaEventCreateWithFlags(&e1, cudaEventDisableTiming);
        cudaEventCreateWithFlags(&eA, cudaEventDisableTiming);
        cudaEventCreateWithFlags(&eB, cudaEventDisableTiming);
    }

    float sqrtD = sqrtf((float)D);
    float scale = 1.f / sqrtf((float)hd);
    int nx4 = rows * D / 4, nw4 = D * D / 4;
    int segs = (M + 1023) / 1024;

    // ---- fork ----
    cudaEventRecord(e0, 0);
    cudaStreamWaitEvent(sA, e0, 0);
    cudaStreamWaitEvent(sB, e0, 0);

    // side A: rowstat -> topk -> proj (independent of main until attn)
    rowstat_kernel<<<(M + 7) / 8, 256, 0, sA>>>(mk, p_r, M, D, sqrtD);
    topk_stage1<<<dim3(segs, 2), 1024, 0, sA>>>(p_r, M, p_cand);
    topk_stage2<<<2, 1024, 0, sA>>>(p_cand, segs * 32, p_pos, p_neg);
    proj_kernel<<<dim3(D / 128, 4), 256, 0, sA>>>(mk, mv, Wk, Wv, p_pos, p_neg,
                                                  p_Kp, p_Kn, p_Vp, p_Vn, D);
    cudaEventRecord(eA, sA);

    // side B: colsum -> qmsign
    colsum1_kernel<<<dim3((D + 255) / 256, 8), 256, 0, sB>>>(Wq, p_part, D);
    colsum2_kernel<<<(D + 255) / 256, 256, 0, sB>>>(p_part, p_wbar, D);
    qmsign_kernel<<<(rows + 7) / 8, 256, 0, sB>>>(x, p_wbar, p_sgn, rows, D);
    cudaEventRecord(eB, sB);

    // main: splits -> gemm1
    split_kernel<<<(nx4 + 255) / 256, 256>>>(x,  p_xhi,  p_xlo,  nx4);
    split_kernel<<<(nw4 + 255) / 256, 256>>>(Wq, p_Wqhi, p_Wqlo, nw4);
    split_kernel<<<(nw4 + 255) / 256, 256>>>(Wo, p_Wohi, p_Wolo, nw4);
    gemm_hmma_kernel<<<dim3(D / 128, rows / 128), 512, GEMM_DSMEM>>>(
        p_xhi, p_xlo, p_Wqhi, p_Wqlo, nullptr, p_qf, D, D);

    // ---- join ----
    cudaStreamWaitEvent(0, eA, 0);
    cudaStreamWaitEvent(0, eB, 0);

    attn_kernel<<<rows, 256>>>(p_qf, p_Kp, p_Kn, p_Vp, p_Vn, p_pos, p_neg, p_sgn,
                               p_chi, p_clo, avg_out, sel_out, D, scale);

    gemm_hmma_kernel<<<dim3(D / 128, rows / 128), 512, GEMM_DSMEM>>>(
        p_chi, p_clo, p_Wohi, p_Wolo, bo, out, D, D);

    ln_kernel<<<rows, 256>>>(out, gamma, beta, D, 1e-5f);
}

// round 10
// speedup vs baseline: 1.5811x; 1.2320x over previous
#include <cuda_runtime.h>
#include <cuda_bf16.h>
#include <math.h>
#include <stdint.h>

// ============================================================================
// CrossAttentionReader — GB300 sm_103a, round 10
//  - round-9 structure (forked graph) +
//  - proj split into proj1 (K-split x8, 256 blocks) + proj2 (combine)
// ============================================================================

#define D_MAX     1024
#define M_MAX     32768
#define ROWS_MAX  2048
#define TKK       32
#define NHEADS    16

// ---- scratch (device globals; no allocation allowed) ----
__device__ float g_r[M_MAX];
__device__ float g_wbar[D_MAX];
__device__ float g_colpart[8 * D_MAX];
__device__ int   g_posidx[TKK];
__device__ int   g_negidx[TKK];
__device__ int   g_sign[ROWS_MAX];
__device__ unsigned long long g_cand[2 * 1024];
__device__ float g_projpart[8 * 4 * TKK * D_MAX];   // [mat*8+ksp][slot][o]
__device__ float g_Kp[TKK * D_MAX];
__device__ float g_Kn[TKK * D_MAX];
__device__ float g_Vp[TKK * D_MAX];
__device__ float g_Vn[TKK * D_MAX];
__device__ float g_qfull[(size_t)ROWS_MAX * D_MAX];
__device__ __nv_bfloat16 g_xhi[(size_t)ROWS_MAX * D_MAX];
__device__ __nv_bfloat16 g_xlo[(size_t)ROWS_MAX * D_MAX];
__device__ __nv_bfloat16 g_ctxhi[(size_t)ROWS_MAX * D_MAX];
__device__ __nv_bfloat16 g_ctxlo[(size_t)ROWS_MAX * D_MAX];
__device__ __nv_bfloat16 g_Wqhi[(size_t)D_MAX * D_MAX];
__device__ __nv_bfloat16 g_Wqlo[(size_t)D_MAX * D_MAX];
__device__ __nv_bfloat16 g_Wohi[(size_t)D_MAX * D_MAX];
__device__ __nv_bfloat16 g_Wolo[(size_t)D_MAX * D_MAX];

// ============================ helpers ===================================
__device__ __forceinline__ uint32_t smem_u32(const void* p) {
    uint32_t a;
    asm("{ .reg .u64 t; cvta.to.shared.u64 t, %1; cvt.u32.u64 %0, t; }" : "=r"(a) : "l"(p));
    return a;
}
__device__ __forceinline__ void ldsm_x4(uint32_t* r, uint32_t addr) {
    asm volatile("ldmatrix.sync.aligned.m8n8.x4.shared.b16 {%0,%1,%2,%3}, [%4];"
                 : "=r"(r[0]), "=r"(r[1]), "=r"(r[2]), "=r"(r[3]) : "r"(addr));
}
__device__ __forceinline__ void mma_bf16(float* d, const uint32_t* a, const uint32_t* b) {
    asm volatile("mma.sync.aligned.m16n8k16.row.col.f32.bf16.bf16.f32 "
                 "{%0,%1,%2,%3}, {%4,%5,%6,%7}, {%8,%9}, {%0,%1,%2,%3};"
                 : "+f"(d[0]), "+f"(d[1]), "+f"(d[2]), "+f"(d[3])
                 : "r"(a[0]), "r"(a[1]), "r"(a[2]), "r"(a[3]), "r"(b[0]), "r"(b[1]));
}
#define CP_ASYNC16(sa, gp) \
    asm volatile("cp.async.cg.shared.global [%0], [%1], 16;" :: "r"(sa), "l"(gp))
#define CP_COMMIT() asm volatile("cp.async.commit_group;" ::: "memory")
#define CP_WAIT(n)  asm volatile("cp.async.wait_group %0;" :: "n"(n) : "memory")

// ---------------------------------------------------------------------------
// split fp32 -> bf16 hi/lo
// ---------------------------------------------------------------------------
__global__ void split_kernel(const float* __restrict__ src, __nv_bfloat16* __restrict__ hi,
                             __nv_bfloat16* __restrict__ lo, int n4) {
    int i = blockIdx.x * 256 + threadIdx.x;
    if (i >= n4) return;
    float4 v = ((const float4*)src)[i];
    __nv_bfloat16 h0 = __float2bfloat16(v.x), h1 = __float2bfloat16(v.y);
    __nv_bfloat16 h2 = __float2bfloat16(v.z), h3 = __float2bfloat16(v.w);
    __nv_bfloat16 l0 = __float2bfloat16(v.x - __bfloat162float(h0));
    __nv_bfloat16 l1 = __float2bfloat16(v.y - __bfloat162float(h1));
    __nv_bfloat16 l2 = __float2bfloat16(v.z - __bfloat162float(h2));
    __nv_bfloat16 l3 = __float2bfloat16(v.w - __bfloat162float(h3));
    ((__nv_bfloat162*)hi)[2 * i]     = __nv_bfloat162(h0, h1);
    ((__nv_bfloat162*)hi)[2 * i + 1] = __nv_bfloat162(h2, h3);
    ((__nv_bfloat162*)lo)[2 * i]     = __nv_bfloat162(l0, l1);
    ((__nv_bfloat162*)lo)[2 * i + 1] = __nv_bfloat162(l2, l3);
}

// ---------------------------------------------------------------------------
// column sum of Wq — two-stage deterministic reduction
// ---------------------------------------------------------------------------
__global__ void colsum1_kernel(const float* __restrict__ W, float* __restrict__ part, int D) {
    int d = blockIdx.x * 256 + threadIdx.x;
    if (d >= D) return;
    int r0 = blockIdx.y * 128;
    float s = 0.f;
    for (int r = r0; r < r0 + 128; r++) s += W[(size_t)r * D + d];
    part[blockIdx.y * D + d] = s;
}
__global__ void colsum2_kernel(const float* __restrict__ part, float* __restrict__ wbar, int D) {
    int d = blockIdx.x * 256 + threadIdx.x;
    if (d >= D) return;
    float s = 0.f;
    #pragma unroll
    for (int i = 0; i < 8; i++) s += part[i * D + d];
    wbar[d] = s;
}

// ---------------------------------------------------------------------------
// per-row r[m] = sum / (sqrtD * norm)
// ---------------------------------------------------------------------------
__global__ void rowstat_kernel(const float* __restrict__ mk, float* __restrict__ r,
                               int M, int D, float sqrtD) {
    int warp = threadIdx.x >> 5, lane = threadIdx.x & 31;
    int m = blockIdx.x * 8 + warp;
    if (m >= M) return;
    const float* row = mk + (size_t)m * D;
    float s = 0.f, ss = 0.f;
    for (int j = lane * 4; j < D; j += 128) {
        float4 v = *(const float4*)(row + j);
        s  += v.x + v.y + v.z + v.w;
        ss += v.x * v.x + v.y * v.y + v.z * v.z + v.w * v.w;
    }
    #pragma unroll
    for (int off = 16; off; off >>= 1) {
        s  += __shfl_xor_sync(0xffffffffu, s, off);
        ss += __shfl_xor_sync(0xffffffffu, ss, off);
    }
    if (lane == 0) r[m] = s / (sqrtD * sqrtf(ss));
}

// ---------------------------------------------------------------------------
// sign(qm) per row
// ---------------------------------------------------------------------------
__global__ void qmsign_kernel(const float* __restrict__ x, const float* __restrict__ wbar,
                              int* __restrict__ sgn, int rows, int D) {
    int warp = threadIdx.x >> 5, lane = threadIdx.x & 31;
    int rn = blockIdx.x * 8 + warp;
    if (rn >= rows) return;
    const float* row = x + (size_t)rn * D;
    float s = 0.f;
    for (int j = lane * 4; j < D; j += 128) {
        float4 v = *(const float4*)(row + j);
        float4 w = *(const float4*)(wbar + j);
        s += v.x * w.x + v.y * w.y + v.z * w.z + v.w * w.w;
    }
    #pragma unroll
    for (int off = 16; off; off >>= 1) s += __shfl_xor_sync(0xffffffffu, s, off);
    if (lane == 0) sgn[rn] = (s >= 0.f) ? 1 : 0;
}

// ---------------------------------------------------------------------------
// topk: 2-stage bitonic. key = (orderable(value) << 32) | ~idx
// ---------------------------------------------------------------------------
__device__ __forceinline__ void bitonic_desc_1024(unsigned long long* s, int tid) {
    for (int k = 2; k <= 1024; k <<= 1) {
        for (int j = k >> 1; j > 0; j >>= 1) {
            int l = tid ^ j;
            if (l > tid) {
                unsigned long long a = s[tid], b = s[l];
                bool desc = ((tid & k) == 0);
                bool sw = desc ? (a < b) : (a > b);
                if (sw) { s[tid] = b; s[l] = a; }
            }
            __syncthreads();
        }
    }
}

__global__ void topk_stage1(const float* __restrict__ r, int M,
                            unsigned long long* __restrict__ cand) {
    int mode = blockIdx.y, seg = blockIdx.x, tid = threadIdx.x;
    __shared__ unsigned long long s[1024];
    int gi = seg * 1024 + tid;
    unsigned long long key = 0ull;
    if (gi < M) {
        uint32_t b = __float_as_uint(r[gi]);
        uint32_t u = (b & 0x80000000u) ? ~b : (b | 0x80000000u);
        if (mode) u = ~u;
        key = ((unsigned long long)u << 32) | (uint32_t)(~gi);
    }
    s[tid] = key;
    __syncthreads();
    bitonic_desc_1024(s, tid);
    if (tid < 32) cand[mode * 1024 + seg * 32 + tid] = s[tid];
}

__global__ void topk_stage2(const unsigned long long* __restrict__ cand, int ncand,
                            int* __restrict__ pos, int* __restrict__ neg) {
    int mode = blockIdx.x, tid = threadIdx.x;
    __shared__ unsigned long long s[1024];
    s[tid] = (tid < ncand) ? cand[mode * 1024 + tid] : 0ull;
    __syncthreads();
    bitonic_desc_1024(s, tid);
    if (tid < 32) {
        int idx = (int)(~(uint32_t)(s[tid] & 0xffffffffu));
        (mode ? neg : pos)[tid] = idx;
    }
}

// ---------------------------------------------------------------------------
// proj stage 1: K-split partials.
// grid (D/128, 4 mats, 8 ksplits); block 256.
// part[(mat*8+ksp)][slot][o] = sum_{d in ksp range} src[idx[slot],d]*W[o,d]
// ---------------------------------------------------------------------------
__global__ void __launch_bounds__(256) proj1_kernel(
        const float* __restrict__ mk, const float* __restrict__ mv,
        const float* __restrict__ Wk, const float* __restrict__ Wv,
        const int* __restrict__ pos, const int* __restrict__ neg,
        float* __restrict__ part, int D) {
    int mat = blockIdx.y, ksp = blockIdx.z;
    const float* src = (mat < 2) ? mk : mv;
    const float* W   = (mat < 2) ? Wk : Wv;
    const int*   idx = (mat & 1) ? neg : pos;
    float* outp = part + ((size_t)(mat * 8 + ksp)) * TKK * D_MAX;

    int o0 = blockIdx.x * 128;
    int kbase = ksp * 128;
    __shared__ float Ks[32][36];
    __shared__ float Ws[32][132];
    __shared__ int   sidx[32];
    int tid = threadIdx.x;
    if (tid < 32) sidx[tid] = idx[tid];
    __syncthreads();

    int tx = tid & 31, ty = tid >> 5;
    float acc[4][4] = {};
    for (int k0 = kbase; k0 < kbase + 128; k0 += 32) {
        {
            int slot = tid >> 3; int d4 = (tid & 7) * 4;
            float4 v = *(const float4*)(src + (size_t)sidx[slot] * D + k0 + d4);
            Ks[d4 + 0][slot] = v.x; Ks[d4 + 1][slot] = v.y;
            Ks[d4 + 2][slot] = v.z; Ks[d4 + 3][slot] = v.w;
        }
        #pragma unroll
        for (int q = 0; q < 4; q++) {
            int l = tid + q * 256; int row = l >> 3; int d4 = (l & 7) * 4;
            float4 v = *(const float4*)(W + (size_t)(o0 + row) * D + k0 + d4);
            Ws[d4 + 0][row] = v.x; Ws[d4 + 1][row] = v.y;
            Ws[d4 + 2][row] = v.z; Ws[d4 + 3][row] = v.w;
        }
        __syncthreads();
        #pragma unroll
        for (int kk = 0; kk < 32; kk++) {
            float a[4], b[4];
            #pragma unroll
            for (int i = 0; i < 4; i++) a[i] = Ks[kk][ty * 4 + i];
            #pragma unroll
            for (int j = 0; j < 4; j++) b[j] = Ws[kk][tx * 4 + j];
            #pragma unroll
            for (int i = 0; i < 4; i++)
                #pragma unroll
                for (int j = 0; j < 4; j++) acc[i][j] += a[i] * b[j];
        }
        __syncthreads();
    }
    #pragma unroll
    for (int i = 0; i < 4; i++)
        #pragma unroll
        for (int j = 0; j < 4; j++)
            outp[(size_t)(ty * 4 + i) * D_MAX + o0 + tx * 4 + j] = acc[i][j];
}

// ---------------------------------------------------------------------------
// proj stage 2: combine 8 K-partials (fixed order -> deterministic)
// grid (4*TKK*D/256); each thread one output element.
// ---------------------------------------------------------------------------
__global__ void proj2_kernel(const float* __restrict__ part,
                             float* __restrict__ Kp, float* __restrict__ Kn,
                             float* __restrict__ Vp, float* __restrict__ Vn, int D) {
    int idx = blockIdx.x * 256 + threadIdx.x;      // over 4*32*1024
    int mat = idx >> 15;                            // /32768
    int rem = idx & 32767;                          // slot*1024 + o
    float s = 0.f;
    #pragma unroll
    for (int ksp = 0; ksp < 8; ksp++)
        s += part[((size_t)(mat * 8 + ksp)) * TKK * D_MAX + rem];
    float* outm = (mat == 0) ? Kp : (mat == 1) ? Kn : (mat == 2) ? Vp : Vn;
    outm[rem] = s;
}

// ---------------------------------------------------------------------------
// HMMA bf16 split-precision GEMM (round-6 best config).
// CTA tile 128x128, BK=32, 16 warps (4m x 4n -> 32x32 per warp), 3-stage.
// ---------------------------------------------------------------------------
#define STR 80
#define OAhi 0
#define OAlo 10240
#define OBhi 20480
#define OBlo 30720
#define BUFB 40960
#define GEMM_DSMEM (3 * BUFB)

__global__ void __launch_bounds__(512) gemm_hmma_kernel(
        const __nv_bfloat16* __restrict__ Ahi, const __nv_bfloat16* __restrict__ Alo,
        const __nv_bfloat16* __restrict__ Bhi, const __nv_bfloat16* __restrict__ Blo,
        const float* __restrict__ bias, float* __restrict__ C, int Kd, int Nc) {
    extern __shared__ __align__(16) uint8_t dsm[];
    int tid = threadIdx.x, wid = tid >> 5, lane = tid & 31;
    int m0g = blockIdx.y * 128, n0g = blockIdx.x * 128;
    int m0w = (wid & 3) * 32, n0w = (wid >> 2) * 32;
    uint32_t sbase = smem_u32(dsm);
    uint32_t a_off = (lane % 16) * STR + (lane / 16) * 16;
    uint32_t b_off = ((lane & 7) + ((lane >> 4) << 3)) * STR + ((lane >> 3) & 1) * 16;
    float acc[2][4][4] = {};

    int nchunk = Kd / 32;
    int lrow = tid >> 2, lseg = tid & 3;
    uint32_t lso = lrow * STR + lseg * 16;
    auto load_chunk = [&](int c, int sel) {
        uint32_t bb = sbase + sel * BUFB;
        int k0 = c * 32;
        size_t ga = (size_t)(m0g + lrow) * Kd + k0 + lseg * 8;
        size_t gb = (size_t)(n0g + lrow) * Kd + k0 + lseg * 8;
        CP_ASYNC16(bb + OAhi + lso, Ahi + ga);
        CP_ASYNC16(bb + OAlo + lso, Alo + ga);
        CP_ASYNC16(bb + OBhi + lso, Bhi + gb);
        CP_ASYNC16(bb + OBlo + lso, Blo + gb);
    };

    load_chunk(0, 0); CP_COMMIT();
    load_chunk(1, 1); CP_COMMIT();

    for (int c = 0; c < nchunk; c++) {
        CP_WAIT(1);
        __syncthreads();
        if (c + 2 < nchunk) load_chunk(c + 2, (c + 2) % 3);
        CP_COMMIT();

        uint32_t bb = sbase + (c % 3) * BUFB;
        #pragma unroll
        for (int ks = 0; ks < 2; ks++) {
            uint32_t ahi[2][4], alo[2][4], bhi[2][4], blo[2][4];
            #pragma unroll
            for (int mf = 0; mf < 2; mf++) {
                uint32_t aaddr = bb + OAhi + (m0w + mf * 16) * STR + ks * 32 + a_off;
                ldsm_x4(ahi[mf], aaddr);
                ldsm_x4(alo[mf], aaddr + (OAlo - OAhi));
            }
            #pragma unroll
            for (int ng = 0; ng < 2; ng++) {
                uint32_t baddr = bb + OBhi + (n0w + ng * 16) * STR + ks * 32 + b_off;
                ldsm_x4(bhi[ng], baddr);
                ldsm_x4(blo[ng], baddr + (OBlo - OBhi));
            }
            #pragma unroll
            for (int mf = 0; mf < 2; mf++)
                #pragma unroll
                for (int nf = 0; nf < 4; nf++)
                    mma_bf16(acc[mf][nf], ahi[mf], &bhi[nf >> 1][(nf & 1) * 2]);
            #pragma unroll
            for (int mf = 0; mf < 2; mf++)
                #pragma unroll
                for (int nf = 0; nf < 4; nf++)
                    mma_bf16(acc[mf][nf], ahi[mf], &blo[nf >> 1][(nf & 1) * 2]);
            #pragma unroll
            for (int mf = 0; mf < 2; mf++)
                #pragma unroll
                for (int nf = 0; nf < 4; nf++)
                    mma_bf16(acc[mf][nf], alo[mf], &bhi[nf >> 1][(nf & 1) * 2]);
        }
    }

    #pragma unroll
    for (int mf = 0; mf < 2; mf++)
        #pragma unroll
        for (int nf = 0; nf < 4; nf++) {
            int col = n0g + n0w + nf * 8 + (lane & 3) * 2;
            float b0 = bias ? bias[col]     : 0.f;
            float b1 = bias ? bias[col + 1] : 0.f;
            int r0 = m0g + m0w + mf * 16 + (lane >> 2);
            float2 v0 = {acc[mf][nf][0] + b0, acc[mf][nf][1] + b1};
            float2 v1 = {acc[mf][nf][2] + b0, acc[mf][nf][3] + b1};
            *(float2*)(C + (size_t)r0 * Nc + col)       = v0;
            *(float2*)(C + (size_t)(r0 + 8) * Nc + col) = v1;
        }
}

// ---------------------------------------------------------------------------
// per-row attention (round-6 best); ctx emitted as bf16 hi/lo split
// ---------------------------------------------------------------------------
__global__ void __launch_bounds__(256) attn_kernel(
        const float* __restrict__ qfull,
        const float* __restrict__ Kp, const float* __restrict__ Kn,
        const float* __restrict__ Vp, const float* __restrict__ Vn,
        const int* __restrict__ pos, const int* __restrict__ neg,
        const int* __restrict__ sgn,
        __nv_bfloat16* __restrict__ ctxhi, __nv_bfloat16* __restrict__ ctxlo,
        float* __restrict__ avg_out, float* __restrict__ sel_out,
        int D, float scale) {
    int rn = blockIdx.x;
    int tid = threadIdx.x;
    int warp = tid >> 5, lane = tid & 31;
    __shared__ float qs[D_MAX];
    __shared__ float sc[NHEADS * TKK];

    int sg = sgn[rn];
    const float* Km = sg ? Kp : Kn;
    const float* Vm = sg ? Vp : Vn;
    const int* idx  = sg ? pos : neg;

    for (int j = tid * 4; j < D; j += 1024)
        *(float4*)(qs + j) = *(const float4*)(qfull + (size_t)rn * D + j);
    __syncthreads();

    for (int t = 0; t < 64; t++) {
        int p = warp * 64 + t;
        int h = p >> 5, k = p & 31;
        const float* kr = Km + (size_t)k * D + h * 64;
        const float* qr = qs + h * 64;
        float v = qr[lane] * kr[lane] + qr[lane + 32] * kr[lane + 32];
        #pragma unroll
        for (int off = 16; off; off >>= 1) v += __shfl_xor_sync(0xffffffffu, v, off);
        if (lane == 0) sc[p] = v * scale;
    }
    __syncthreads();

    #pragma unroll
    for (int hh = warp * 2; hh < warp * 2 + 2; hh++) {
        float v = sc[hh * 32 + lane];
        float mx = v;
        #pragma unroll
        for (int off = 16; off; off >>= 1) mx = fmaxf(mx, __shfl_xor_sync(0xffffffffu, mx, off));
        float e = expf(v - mx);
        float s = e;
        #pragma unroll
        for (int off = 16; off; off >>= 1) s += __shfl_xor_sync(0xffffffffu, s, off);
        sc[hh * 32 + lane] = e / s;
    }
    __syncthreads();

    if (tid < 32) {
        if (avg_out) {
            float a = 0.f;
            #pragma unroll
            for (int h = 0; h < NHEADS; h++) a += sc[h * 32 + tid];
            avg_out[(size_t)rn * TKK + tid] = a * (1.f / NHEADS);
        }
        if (sel_out) sel_out[(size_t)rn * TKK + tid] = (float)idx[tid];
    }

    for (int o = tid; o < D; o += 256) {
        int h = o >> 6;
        const float* arow = sc + h * 32;
        float a = 0.f;
        #pragma unroll
        for (int k = 0; k < TKK; k++) a += arow[k] * Vm[(size_t)k * D + o];
        __nv_bfloat16 hi = __float2bfloat16(a);
        __nv_bfloat16 lo = __float2bfloat16(a - __bfloat162float(hi));
        ctxhi[(size_t)rn * D + o] = hi;
        ctxlo[(size_t)rn * D + o] = lo;
    }
}

// ---------------------------------------------------------------------------
// LayerNorm in-place per row
// ---------------------------------------------------------------------------
__global__ void __launch_bounds__(256) ln_kernel(
        float* __restrict__ out, const float* __restrict__ gamma,
        const float* __restrict__ beta, int D, float eps) {
    int rn = blockIdx.x;
    float* row = out + (size_t)rn * D;
    int tid = threadIdx.x;
    int warp = tid >> 5, lane = tid & 31;
    __shared__ float ssum[8], ssq[8];

    float s = 0.f, ss = 0.f;
    for (int j = tid * 4; j < D; j += 1024) {
        float4 v = *(const float4*)(row + j);
        s  += v.x + v.y + v.z + v.w;
        ss += v.x * v.x + v.y * v.y + v.z * v.z + v.w * v.w;
    }
    #pragma unroll
    for (int off = 16; off; off >>= 1) {
        s  += __shfl_xor_sync(0xffffffffu, s, off);
        ss += __shfl_xor_sync(0xffffffffu, ss, off);
    }
    if (lane == 0) { ssum[warp] = s; ssq[warp] = ss; }
    __syncthreads();
    if (tid == 0) {
        float ts = 0.f, tq = 0.f;
        #pragma unroll
        for (int w = 0; w < 8; w++) { ts += ssum[w]; tq += ssq[w]; }
        ssum[0] = ts; ssq[0] = tq;
    }
    __syncthreads();
    float mu = ssum[0] / D;
    float var = ssq[0] / D - mu * mu;
    float rstd = rsqrtf(var + eps);
    for (int j = tid * 4; j < D; j += 1024) {
        float4 v = *(const float4*)(row + j);
        float4 g = *(const float4*)(gamma + j);
        float4 bb = *(const float4*)(beta + j);
        v.x = (v.x - mu) * rstd * g.x + bb.x;
        v.y = (v.y - mu) * rstd * g.y + bb.y;
        v.z = (v.z - mu) * rstd * g.z + bb.z;
        v.w = (v.w - mu) * rstd * g.w + bb.w;
        *(float4*)(row + j) = v;
    }
}

// ---------------------------------------------------------------------------
// launch — forked graph
// ---------------------------------------------------------------------------
extern "C" void kernel_launch(void* const* d_in, const int* in_sizes, int n_in,
                              void* d_out, int out_size) {
    const float* x     = (const float*)d_in[0];
    const float* mk    = (const float*)d_in[1];
    const float* mv    = (const float*)d_in[2];
    const float* Wq    = (const float*)d_in[3];
    const float* Wk    = (const float*)d_in[4];
    const float* Wv    = (const float*)d_in[5];
    const float* Wo    = (const float*)d_in[6];
    const float* bo    = (const float*)d_in[7];
    const float* gamma = (const float*)d_in[8];
    const float* beta  = (const float*)d_in[9];

    int D    = in_sizes[7];
    int rows = in_sizes[0] / D;           // B*N
    int M    = in_sizes[1] / D;
    int hd   = D / NHEADS;

    float* out = (float*)d_out;
    float* avg_out = nullptr;
    float* sel_out = nullptr;
    if ((long long)out_size >= (long long)rows * (D + 2 * TKK)) {
        avg_out = out + (size_t)rows * D;
        sel_out = avg_out + (size_t)rows * TKK;
    }

    float *p_r, *p_wbar, *p_part, *p_ppart, *p_Kp, *p_Kn, *p_Vp, *p_Vn, *p_qf;
    int *p_pos, *p_neg, *p_sgn;
    unsigned long long* p_cand;
    __nv_bfloat16 *p_xhi, *p_xlo, *p_chi, *p_clo, *p_Wqhi, *p_Wqlo, *p_Wohi, *p_Wolo;
    cudaGetSymbolAddress((void**)&p_r,    g_r);
    cudaGetSymbolAddress((void**)&p_wbar, g_wbar);
    cudaGetSymbolAddress((void**)&p_part, g_colpart);
    cudaGetSymbolAddress((void**)&p_ppart, g_projpart);
    cudaGetSymbolAddress((void**)&p_pos,  g_posidx);
    cudaGetSymbolAddress((void**)&p_neg,  g_negidx);
    cudaGetSymbolAddress((void**)&p_sgn,  g_sign);
    cudaGetSymbolAddress((void**)&p_cand, g_cand);
    cudaGetSymbolAddress((void**)&p_Kp,   g_Kp);
    cudaGetSymbolAddress((void**)&p_Kn,   g_Kn);
    cudaGetSymbolAddress((void**)&p_Vp,   g_Vp);
    cudaGetSymbolAddress((void**)&p_Vn,   g_Vn);
    cudaGetSymbolAddress((void**)&p_qf,   g_qfull);
    cudaGetSymbolAddress((void**)&p_xhi,  g_xhi);
    cudaGetSymbolAddress((void**)&p_xlo,  g_xlo);
    cudaGetSymbolAddress((void**)&p_chi,  g_ctxhi);
    cudaGetSymbolAddress((void**)&p_clo,  g_ctxlo);
    cudaGetSymbolAddress((void**)&p_Wqhi, g_Wqhi);
    cudaGetSymbolAddress((void**)&p_Wqlo, g_Wqlo);
    cudaGetSymbolAddress((void**)&p_Wohi, g_Wohi);
    cudaGetSymbolAddress((void**)&p_Wolo, g_Wolo);

    cudaFuncSetAttribute(gemm_hmma_kernel, cudaFuncAttributeMaxDynamicSharedMemorySize,
                         GEMM_DSMEM);

    static cudaStream_t sA = nullptr, sB = nullptr;
    static cudaEvent_t e0 = nullptr, eA = nullptr, eB = nullptr;
    if (!sA) {
        cudaStreamCreateWithFlags(&sA, cudaStreamNonBlocking);
        cudaStreamCreateWithFlags(&sB, cudaStreamNonBlocking);
        cudaEventCreateWithFlags(&e0, cudaEventDisableTiming);
        cudaEventCreateWithFlags(&eA, cudaEventDisableTiming);
        cudaEventCreateWithFlags(&eB, cudaEventDisableTiming);
    }

    float sqrtD = sqrtf((float)D);
    float scale = 1.f / sqrtf((float)hd);
    int nx4 = rows * D / 4, nw4 = D * D / 4;
    int segs = (M + 1023) / 1024;

    // ---- fork ----
    cudaEventRecord(e0, 0);
    cudaStreamWaitEvent(sA, e0, 0);
    cudaStreamWaitEvent(sB, e0, 0);

    // side A: rowstat -> topk -> proj1 -> proj2
    rowstat_kernel<<<(M + 7) / 8, 256, 0, sA>>>(mk, p_r, M, D, sqrtD);
    topk_stage1<<<dim3(segs, 2), 1024, 0, sA>>>(p_r, M, p_cand);
    topk_stage2<<<2, 1024, 0, sA>>>(p_cand, segs * 32, p_pos, p_neg);
    proj1_kernel<<<dim3(D / 128, 4, 8), 256, 0, sA>>>(mk, mv, Wk, Wv, p_pos, p_neg,
                                                      p_ppart, D);
    proj2_kernel<<<(4 * TKK * D_MAX) / 256, 256, 0, sA>>>(p_ppart, p_Kp, p_Kn,
                                                          p_Vp, p_Vn, D);
    cudaEventRecord(eA, sA);

    // side B: colsum -> qmsign
    colsum1_kernel<<<dim3((D + 255) / 256, 8), 256, 0, sB>>>(Wq, p_part, D);
    colsum2_kernel<<<(D + 255) / 256, 256, 0, sB>>>(p_part, p_wbar, D);
    qmsign_kernel<<<(rows + 7) / 8, 256, 0, sB>>>(x, p_wbar, p_sgn, rows, D);
    cudaEventRecord(eB, sB);

    // main: splits -> gemm1
    split_kernel<<<(nx4 + 255) / 256, 256>>>(x,  p_xhi,  p_xlo,  nx4);
    split_kernel<<<(nw4 + 255) / 256, 256>>>(Wq, p_Wqhi, p_Wqlo, nw4);
    split_kernel<<<(nw4 + 255) / 256, 256>>>(Wo, p_Wohi, p_Wolo, nw4);
    gemm_hmma_kernel<<<dim3(D / 128, rows / 128), 512, GEMM_DSMEM>>>(
        p_xhi, p_xlo, p_Wqhi, p_Wqlo, nullptr, p_qf, D, D);

    // ---- join ----
    cudaStreamWaitEvent(0, eA, 0);
    cudaStreamWaitEvent(0, eB, 0);

    attn_kernel<<<rows, 256>>>(p_qf, p_Kp, p_Kn, p_Vp, p_Vn, p_pos, p_neg, p_sgn,
                               p_chi, p_clo, avg_out, sel_out, D, scale);

    gemm_hmma_kernel<<<dim3(D / 128, rows / 128), 512, GEMM_DSMEM>>>(
        p_chi, p_clo, p_Wohi, p_Wolo, bo, out, D, D);

    ln_kernel<<<rows, 256>>>(out, gamma, beta, D, 1e-5f);
}